// round 13
// baseline (speedup 1.0000x reference)
#include <cuda_runtime.h>
#include <cuda_fp16.h>
#include <math.h>
#include <stdint.h>

#define B_ 16
#define L_ 256
#define H_ 512
#define NH_ 8
#define DH_ 64
#define NL_ 6
#define NTOK_ 10000
#define P_ 4
#define KW_ 9
#define DFF_ 2048
#define BL_ (B_ * L_)

// ---------------- device scratch (fp32) ----------------
__device__ float g_h[BL_ * H_];
__device__ float g_pcb[1024];
__device__ int   g_mask[BL_];
// ---------------- device scratch (fp16) ----------------
__device__ __half g_head16[B_ * L_ * L_];
__device__ __half g_headT16[B_ * L_ * L_];
__device__ __half g_h16[BL_ * H_];
__device__ __half g_hn16[BL_ * H_];
__device__ __half g_pc16[BL_ * 1024];
__device__ __half g_qkv16[BL_ * 3 * H_];
__device__ __half g_ctx16[BL_ * H_];
__device__ __half g_ff16[BL_ * DFF_];
// fp16 weights
__device__ __half g_convT16[P_ * H_ * KW_ * H_];
__device__ __half g_qkvw16[NL_ * 3 * H_ * H_];
__device__ __half g_outw16[NL_ * H_ * H_];
__device__ __half g_ff1w16[NL_ * DFF_ * H_];
__device__ __half g_ff2w16[NL_ * H_ * DFF_];
__device__ __half g_pcw16[1024 * H_];
__device__ __half g_emb16[NTOK_ * H_];

// ================= helpers =================
__device__ __forceinline__ uint32_t pack_h2(float x, float y) {
    __half2 h = __floats2half2_rn(x, y);
    return *reinterpret_cast<uint32_t*>(&h);
}
__device__ __forceinline__ uint32_t smem_u32(const void* p) {
    uint32_t a;
    asm("{ .reg .u64 t; cvta.to.shared.u64 t, %1; cvt.u32.u64 %0, t; }" : "=r"(a) : "l"(p));
    return a;
}
__device__ __forceinline__ uint32_t sw128(uint32_t x) { return x ^ ((x >> 3) & 0x70); }

__device__ __forceinline__ void mma_f16(float c[4], uint32_t a0, uint32_t a1,
                                        uint32_t a2, uint32_t a3,
                                        uint32_t b0, uint32_t b1) {
    asm volatile(
        "mma.sync.aligned.m16n8k16.row.col.f32.f16.f16.f32 "
        "{%0,%1,%2,%3}, {%4,%5,%6,%7}, {%8,%9}, {%0,%1,%2,%3};\n"
        : "+f"(c[0]), "+f"(c[1]), "+f"(c[2]), "+f"(c[3])
        : "r"(a0), "r"(a1), "r"(a2), "r"(a3), "r"(b0), "r"(b1));
}
__device__ __forceinline__ void ldsm_x4(uint32_t& r0, uint32_t& r1, uint32_t& r2,
                                        uint32_t& r3, uint32_t addr) {
    asm volatile("ldmatrix.sync.aligned.m8n8.x4.shared.b16 {%0,%1,%2,%3}, [%4];"
                 : "=r"(r0), "=r"(r1), "=r"(r2), "=r"(r3) : "r"(addr));
}
__device__ __forceinline__ void ldsm_x4_t(uint32_t& r0, uint32_t& r1, uint32_t& r2,
                                          uint32_t& r3, uint32_t addr) {
    asm volatile("ldmatrix.sync.aligned.m8n8.x4.trans.shared.b16 {%0,%1,%2,%3}, [%4];"
                 : "=r"(r0), "=r"(r1), "=r"(r2), "=r"(r3) : "r"(addr));
}
__device__ __forceinline__ void cp16(uint32_t dst, const __half* src, int sz) {
    asm volatile("cp.async.cg.shared.global [%0], [%1], 16, %2;"
                 :: "r"(dst), "l"(__cvta_generic_to_global(src)), "r"(sz));
}

// ---------------- fused fp32 -> fp16 conversion ----------------
struct CvtJobs {
    const float* src[7];
    __half* dst[7];
    int n4[7];
};
__global__ void cvt_multi(CvtJobs j, int total4) {
    int i = blockIdx.x * 256 + threadIdx.x;
    if (i >= total4) return;
    int s = 0, base = 0;
    while (i - base >= j.n4[s]) { base += j.n4[s]; s++; }
    int o = i - base;
    float4 v = *(const float4*)(j.src[s] + (long)o * 4);
    *(uint2*)(j.dst[s] + (long)o * 4) = make_uint2(pack_h2(v.x, v.y), pack_h2(v.z, v.w));
}

// conv weights: w[p][k][ci][co] -> wt16[p][co][k*H+ci]
__global__ void convw_transpose16(const float* __restrict__ w, __half* __restrict__ wt) {
    __shared__ float t[32][33];
    int pk = blockIdx.z;
    int p = pk / KW_, k = pk % KW_;
    int ci0 = blockIdx.y * 32, co0 = blockIdx.x * 32;
    t[threadIdx.y][threadIdx.x] =
        w[((long)pk * H_ + ci0 + threadIdx.y) * H_ + co0 + threadIdx.x];
    __syncthreads();
    wt[((long)p * H_ + co0 + threadIdx.y) * (KW_ * H_) + k * H_ + ci0 + threadIdx.x] =
        __float2half(t[threadIdx.x][threadIdx.y]);
}

__global__ void concat_bias(const float* __restrict__ a, const float* __restrict__ b,
                            float* __restrict__ o) {
    int i = blockIdx.x * 256 + threadIdx.x;
    if (i < 512) o[i] = a[i];
    else if (i < 1024) o[i] = b[i - 512];
}

// =====================================================================
// fp16 GEMM: 256 threads, cp.async NS-stage, SW128 + ldmatrix, 2 CTAs/SM.
// =====================================================================
template <int WM, int WN, int MF, int NF, int NS>
__global__ __launch_bounds__(256, 2) void gemm_h(
    const __half* __restrict__ A, const __half* __restrict__ W,
    const float* __restrict__ bias, const float* __restrict__ resid,
    float* __restrict__ C, __half* __restrict__ C16,
    const int* __restrict__ cmask,
    int M, int N, int Kd, int strideA, int strideW,
    long sA, long sB, long sC,
    int epilogue, int conv_mode)
{
    constexpr int BM = WM * MF * 16;
    constexpr int BN = WN * NF * 8;
    constexpr int ABYTES = BM * 128;
    constexpr int BBYTES = BN * 128;
    constexpr int STAGEB = ABYTES + BBYTES;
    constexpr int AIT = BM * 8 / 256;
    constexpr int BIT = BN * 8 / 256;

    extern __shared__ char smem[];
    uint32_t sb = smem_u32(smem);

    int bz = blockIdx.z;
    A += (long)bz * sA;
    W += (long)bz * sB;
    if (C) C += (long)bz * sC;
    if (C16) C16 += (long)bz * sC;
    if (resid) resid += (long)bz * sC;

    const int tid = threadIdx.x;
    const int warp = tid >> 5, lane = tid & 31;
    const int wm = warp / WN;
    const int wn = warp % WN;
    const int grp = lane >> 2, tig = lane & 3;
    const int row0 = blockIdx.y * BM;
    const int col0 = blockIdx.x * BN;

    uint32_t mbits[AIT];
    if (conv_mode) {
#pragma unroll
        for (int it = 0; it < AIT; it++) {
            int r = (tid + 256 * it) >> 3;
            int arow = row0 + r;
            int bb = arow >> 8, base = arow & 255;
            uint32_t bits = 0;
#pragma unroll
            for (int s = 0; s < 9; s++) {
                int ll = base + s - 4;
                if (ll >= 0 && ll < 256 && cmask[bb * 256 + ll] != 0)
                    bits |= 1u << s;
            }
            mbits[it] = bits;
        }
    }

    float acc[MF][NF][4];
#pragma unroll
    for (int i = 0; i < MF; i++)
#pragma unroll
        for (int j = 0; j < NF; j++)
#pragma unroll
            for (int r = 0; r < 4; r++) acc[i][j][r] = 0.f;

    const int nchunks = Kd >> 6;

    auto issue = [&](int c) {
        if (c < nchunks) {
            uint32_t abase = sb + (c % NS) * STAGEB;
            uint32_t bbase = abase + ABYTES;
            const int k0 = c << 6;
#pragma unroll
            for (int it = 0; it < AIT; it++) {
                int idx = tid + 256 * it;
                int r = idx >> 3, q = idx & 7;
                int arow = row0 + r;
                const __half* src;
                int sz = 16;
                if (conv_mode) {
                    int s = c >> 3;
                    int bb = arow >> 8;
                    int ll = (arow & 255) + s - 4;
                    int lc = min(max(ll, 0), 255);
                    src = A + ((long)(bb * 256 + lc) * 512) + (k0 & 511) + q * 8;
                    sz = ((mbits[it] >> s) & 1u) ? 16 : 0;
                } else {
                    src = A + (long)arow * strideA + k0 + q * 8;
                }
                cp16(abase + sw128(r * 128 + q * 16), src, sz);
            }
#pragma unroll
            for (int it = 0; it < BIT; it++) {
                int idx = tid + 256 * it;
                int r = idx >> 3, q = idx & 7;
                int bn = col0 + r;
                int bc = min(bn, N - 1);
                int sz = (bn < N) ? 16 : 0;
                cp16(bbase + sw128(r * 128 + q * 16),
                     W + (long)bc * strideW + k0 + q * 8, sz);
            }
        }
        asm volatile("cp.async.commit_group;" ::: "memory");
    };

#pragma unroll
    for (int s = 0; s < NS - 1; s++) issue(s);

    const int arow_l = (lane & 7) + ((lane >> 3) & 1) * 8;
    const int akh = (lane >> 4) & 1;
    const int brow_l = (lane & 7) + ((lane >> 4) & 1) * 8;
    const int bkh = (lane >> 3) & 1;

    for (int c = 0; c < nchunks; c++) {
        asm volatile("cp.async.wait_group %0;" :: "n"(NS - 2) : "memory");
        __syncthreads();
        issue(c + NS - 1);

        const uint32_t Ab = sb + (c % NS) * STAGEB;
        const uint32_t Bb = Ab + ABYTES;
#pragma unroll
        for (int ks = 0; ks < 4; ks++) {
            uint32_t a[MF][4];
#pragma unroll
            for (int mf = 0; mf < MF; mf++) {
                int row = (wm * MF + mf) * 16 + arow_l;
                ldsm_x4(a[mf][0], a[mf][1], a[mf][2], a[mf][3],
                        Ab + sw128(row * 128 + ks * 32 + akh * 16));
            }
            uint32_t b[NF][2];
#pragma unroll
            for (int ng = 0; ng < NF / 2; ng++) {
                int nrow = (wn * NF + 2 * ng) * 8 + brow_l;
                uint32_t r0, r1, r2, r3;
                ldsm_x4(r0, r1, r2, r3,
                        Bb + sw128(nrow * 128 + ks * 32 + bkh * 16));
                b[2 * ng][0] = r0; b[2 * ng][1] = r1;
                b[2 * ng + 1][0] = r2; b[2 * ng + 1][1] = r3;
            }
#pragma unroll
            for (int mf = 0; mf < MF; mf++)
#pragma unroll
                for (int nf = 0; nf < NF; nf++)
                    mma_f16(acc[mf][nf], a[mf][0], a[mf][1], a[mf][2], a[mf][3],
                            b[nf][0], b[nf][1]);
        }
    }

    // ---- epilogue ----
#pragma unroll
    for (int mf = 0; mf < MF; mf++) {
        int r0 = row0 + (wm * MF + mf) * 16 + grp;
        int r1 = r0 + 8;
#pragma unroll
        for (int nf = 0; nf < NF; nf++) {
            int cb = col0 + (wn * NF + nf) * 8 + tig * 2;
            if (cb >= N) continue;
            float v0 = acc[mf][nf][0], v1 = acc[mf][nf][1];
            float v2 = acc[mf][nf][2], v3 = acc[mf][nf][3];
            if (bias) {
                float b0 = bias[cb], b1 = bias[cb + 1];
                v0 += b0; v1 += b1; v2 += b0; v3 += b1;
            }
            if (epilogue == 1) {
                v0 = (v0 > 0.f) ? v0 : 0.01f * v0;
                v1 = (v1 > 0.f) ? v1 : 0.01f * v1;
                v2 = (v2 > 0.f) ? v2 : 0.01f * v2;
                v3 = (v3 > 0.f) ? v3 : 0.01f * v3;
            }
            if (resid) {
                v0 += resid[(long)r0 * N + cb]; v1 += resid[(long)r0 * N + cb + 1];
                v2 += resid[(long)r1 * N + cb]; v3 += resid[(long)r1 * N + cb + 1];
            }
            if (C) {
                *(float2*)(C + (long)r0 * N + cb) = make_float2(v0, v1);
                *(float2*)(C + (long)r1 * N + cb) = make_float2(v2, v3);
            }
            if (C16) {
                *(__half2*)(C16 + (long)r0 * N + cb) = __floats2half2_rn(v0, v1);
                *(__half2*)(C16 + (long)r1 * N + cb) = __floats2half2_rn(v2, v3);
            }
        }
    }
}

// =====================================================================
// tensor-core attention: 2 q-tiles (128 rows) per CTA, K/V resident.
// =====================================================================
#define ATT_SM_Q 0
#define ATT_SM_K 8192
#define ATT_SM_V 40960
#define ATT_SM_P 73728
#define ATT_SM_RED 106496
#define ATT_SMEM (106496 + 2048)

__device__ __forceinline__ uint32_t swp(int r, int c2) {
    return (uint32_t)(r * 512 + (c2 ^ ((r & 7) << 4)));
}

__global__ __launch_bounds__(256) void attn_mma(
    const __half* __restrict__ qkv, const __half* __restrict__ head,
    const __half* __restrict__ headT, const int* __restrict__ mask,
    const float* __restrict__ relw, int layer, __half* __restrict__ ctx)
{
    extern __shared__ char sma[];
    uint32_t sbase = smem_u32(sma);
    const int b = blockIdx.z, hh = blockIdx.y;
    const int tid = threadIdx.x, warp = tid >> 5, lane = tid & 31;
    const int wm = warp >> 2, wn = warp & 3;
    const int r4 = lane >> 2, c2 = (lane & 3) * 2;

    const __half* qb = qkv + (long)b * L_ * 1536 + hh * 64;
    const __half* kb = qb + 512;
    const __half* vb = qb + 1024;

    // K/V resident for both q-tiles
    for (int idx = tid; idx < 256 * 8; idx += 256) {
        int r = idx >> 3, q = idx & 7;
        cp16(sbase + ATT_SM_K + sw128(r * 128 + q * 16), kb + (long)r * 1536 + q * 8, 16);
        cp16(sbase + ATT_SM_V + sw128(r * 128 + q * 16), vb + (long)r * 1536 + q * 8, 16);
    }

    float w0, w1;
    {
        float a0v = relw[(layer * NH_ + hh) * 2 + 0];
        float a1v = relw[(layer * NH_ + hh) * 2 + 1];
        float mv = fmaxf(a0v, a1v);
        float e0 = __expf(a0v - mv), e1 = __expf(a1v - mv);
        w0 = e0 / (e0 + e1); w1 = e1 / (e0 + e1);
    }

    for (int tq = 0; tq < 2; tq++) {
        const int i0 = blockIdx.x * 128 + tq * 64;

        for (int idx = tid; idx < 64 * 8; idx += 256) {
            int r = idx >> 3, q = idx & 7;
            cp16(sbase + ATT_SM_Q + sw128(r * 128 + q * 16),
                 qb + (long)(i0 + r) * 1536 + q * 8, 16);
        }
        asm volatile("cp.async.commit_group;" ::: "memory");
        asm volatile("cp.async.wait_group 0;" ::: "memory");
        __syncthreads();

        float acc[2][8][4];
#pragma unroll
        for (int i = 0; i < 2; i++)
#pragma unroll
            for (int j = 0; j < 8; j++)
#pragma unroll
                for (int r = 0; r < 4; r++) acc[i][j][r] = 0.f;

#pragma unroll
        for (int kk = 0; kk < 4; kk++) {
            uint32_t a[2][4];
#pragma unroll
            for (int mf = 0; mf < 2; mf++) {
                int row = wm * 32 + mf * 16 + (lane & 7) + ((lane >> 3) & 1) * 8;
                int kh = (lane >> 4) & 1;
                ldsm_x4(a[mf][0], a[mf][1], a[mf][2], a[mf][3],
                        sbase + ATT_SM_Q + sw128(row * 128 + kk * 32 + kh * 16));
            }
            uint32_t bf[8][2];
#pragma unroll
            for (int ng = 0; ng < 4; ng++) {
                int nrow = wn * 64 + ng * 16 + (lane & 7) + ((lane >> 4) & 1) * 8;
                int kh = (lane >> 3) & 1;
                uint32_t r0, r1, r2, r3;
                ldsm_x4(r0, r1, r2, r3,
                        sbase + ATT_SM_K + sw128(nrow * 128 + kk * 32 + kh * 16));
                bf[2 * ng][0] = r0; bf[2 * ng][1] = r1;
                bf[2 * ng + 1][0] = r2; bf[2 * ng + 1][1] = r3;
            }
#pragma unroll
            for (int mf = 0; mf < 2; mf++)
#pragma unroll
                for (int nf = 0; nf < 8; nf++)
                    mma_f16(acc[mf][nf], a[mf][0], a[mf][1], a[mf][2], a[mf][3],
                            bf[nf][0], bf[nf][1]);
        }

#pragma unroll
        for (int nf = 0; nf < 8; nf++) {
            int j = wn * 64 + nf * 8 + c2;
            int m0 = mask[b * L_ + j], m1 = mask[b * L_ + j + 1];
#pragma unroll
            for (int mf = 0; mf < 2; mf++) {
                int ia = i0 + wm * 32 + mf * 16 + r4;
                float2 hd = __half22float2(*(const __half2*)(head + ((long)(b * L_ + ia)) * L_ + j));
                float2 ht = __half22float2(*(const __half2*)(headT + ((long)(b * L_ + ia)) * L_ + j));
                float s0 = acc[mf][nf][0] * 0.125f + w0 * hd.x + w1 * ht.x;
                float s1 = acc[mf][nf][1] * 0.125f + w0 * hd.y + w1 * ht.y;
                acc[mf][nf][0] = m0 ? s0 : -1e30f;
                acc[mf][nf][1] = m1 ? s1 : -1e30f;
                int ib = ia + 8;
                float2 hd2 = __half22float2(*(const __half2*)(head + ((long)(b * L_ + ib)) * L_ + j));
                float2 ht2 = __half22float2(*(const __half2*)(headT + ((long)(b * L_ + ib)) * L_ + j));
                float s2 = acc[mf][nf][2] * 0.125f + w0 * hd2.x + w1 * ht2.x;
                float s3 = acc[mf][nf][3] * 0.125f + w0 * hd2.y + w1 * ht2.y;
                acc[mf][nf][2] = m0 ? s2 : -1e30f;
                acc[mf][nf][3] = m1 ? s3 : -1e30f;
            }
        }

        float* redm = (float*)(sma + ATT_SM_RED);
        float* reds = redm + 256;
        float mx[4];
#pragma unroll
        for (int mf = 0; mf < 2; mf++)
#pragma unroll
            for (int hf = 0; hf < 2; hf++) {
                float m = -1e30f;
#pragma unroll
                for (int nf = 0; nf < 8; nf++)
                    m = fmaxf(m, fmaxf(acc[mf][nf][2 * hf], acc[mf][nf][2 * hf + 1]));
                mx[mf * 2 + hf] = m;
            }
#pragma unroll
        for (int ri = 0; ri < 4; ri++) {
            mx[ri] = fmaxf(mx[ri], __shfl_xor_sync(0xffffffffu, mx[ri], 1));
            mx[ri] = fmaxf(mx[ri], __shfl_xor_sync(0xffffffffu, mx[ri], 2));
        }
        if ((lane & 3) == 0) {
#pragma unroll
            for (int mf = 0; mf < 2; mf++)
#pragma unroll
                for (int hf = 0; hf < 2; hf++)
                    redm[wn * 64 + wm * 32 + mf * 16 + hf * 8 + r4] = mx[mf * 2 + hf];
        }
        __syncthreads();
        float MX[4];
#pragma unroll
        for (int mf = 0; mf < 2; mf++)
#pragma unroll
            for (int hf = 0; hf < 2; hf++) {
                int row = wm * 32 + mf * 16 + hf * 8 + r4;
                float m = redm[row];
                m = fmaxf(m, redm[64 + row]);
                m = fmaxf(m, redm[128 + row]);
                m = fmaxf(m, redm[192 + row]);
                MX[mf * 2 + hf] = m;
            }
        float sm[4] = {0.f, 0.f, 0.f, 0.f};
#pragma unroll
        for (int mf = 0; mf < 2; mf++)
#pragma unroll
            for (int nf = 0; nf < 8; nf++)
#pragma unroll
                for (int hf = 0; hf < 2; hf++) {
                    float e0 = __expf(acc[mf][nf][2 * hf] - MX[mf * 2 + hf]);
                    float e1 = __expf(acc[mf][nf][2 * hf + 1] - MX[mf * 2 + hf]);
                    acc[mf][nf][2 * hf] = e0;
                    acc[mf][nf][2 * hf + 1] = e1;
                    sm[mf * 2 + hf] += e0 + e1;
                }
#pragma unroll
        for (int ri = 0; ri < 4; ri++) {
            sm[ri] += __shfl_xor_sync(0xffffffffu, sm[ri], 1);
            sm[ri] += __shfl_xor_sync(0xffffffffu, sm[ri], 2);
        }
        if ((lane & 3) == 0) {
#pragma unroll
            for (int mf = 0; mf < 2; mf++)
#pragma unroll
                for (int hf = 0; hf < 2; hf++)
                    reds[wn * 64 + wm * 32 + mf * 16 + hf * 8 + r4] = sm[mf * 2 + hf];
        }
        __syncthreads();
        float inv[4];
#pragma unroll
        for (int mf = 0; mf < 2; mf++)
#pragma unroll
            for (int hf = 0; hf < 2; hf++) {
                int row = wm * 32 + mf * 16 + hf * 8 + r4;
                float t = reds[row] + reds[64 + row] + reds[128 + row] + reds[192 + row];
                inv[mf * 2 + hf] = 1.f / t;
            }

#pragma unroll
        for (int mf = 0; mf < 2; mf++)
#pragma unroll
            for (int nf = 0; nf < 8; nf++) {
                int rowa = wm * 32 + mf * 16 + r4;
                int j = wn * 64 + nf * 8 + c2;
                *(uint32_t*)(sma + ATT_SM_P + swp(rowa, j * 2)) =
                    pack_h2(acc[mf][nf][0] * inv[mf * 2], acc[mf][nf][1] * inv[mf * 2]);
                *(uint32_t*)(sma + ATT_SM_P + swp(rowa + 8, j * 2)) =
                    pack_h2(acc[mf][nf][2] * inv[mf * 2 + 1], acc[mf][nf][3] * inv[mf * 2 + 1]);
            }
        __syncthreads();

        float oacc[2][2][4];
#pragma unroll
        for (int i = 0; i < 2; i++)
#pragma unroll
            for (int j = 0; j < 2; j++)
#pragma unroll
                for (int r = 0; r < 4; r++) oacc[i][j][r] = 0.f;

#pragma unroll
        for (int kk = 0; kk < 16; kk++) {
            uint32_t a[2][4];
#pragma unroll
            for (int mf = 0; mf < 2; mf++) {
                int row = wm * 32 + mf * 16 + (lane & 7) + ((lane >> 3) & 1) * 8;
                int kh = (lane >> 4) & 1;
                ldsm_x4(a[mf][0], a[mf][1], a[mf][2], a[mf][3],
                        sbase + ATT_SM_P + swp(row, kk * 32 + kh * 16));
            }
            uint32_t bf[2][2];
            {
                int kvrow = kk * 16 + (lane & 7) + ((lane >> 3) & 1) * 8;
                int nb = wn * 16 + ((lane >> 4) & 1) * 8;
                uint32_t r0, r1, r2, r3;
                ldsm_x4_t(r0, r1, r2, r3,
                          sbase + ATT_SM_V + sw128(kvrow * 128 + nb * 2));
                bf[0][0] = r0; bf[0][1] = r1; bf[1][0] = r2; bf[1][1] = r3;
            }
#pragma unroll
            for (int mf = 0; mf < 2; mf++)
#pragma unroll
                for (int nf = 0; nf < 2; nf++)
                    mma_f16(oacc[mf][nf], a[mf][0], a[mf][1], a[mf][2], a[mf][3],
                            bf[nf][0], bf[nf][1]);
        }

#pragma unroll
        for (int mf = 0; mf < 2; mf++)
#pragma unroll
            for (int nf = 0; nf < 2; nf++) {
                int row = i0 + wm * 32 + mf * 16 + r4;
                int d = wn * 16 + nf * 8 + c2;
                __half* dst = ctx + ((long)(b * L_) + row) * H_ + hh * 64 + d;
                *(__half2*)dst = __floats2half2_rn(oacc[mf][nf][0], oacc[mf][nf][1]);
                *(__half2*)(dst + 8 * H_) = __floats2half2_rn(oacc[mf][nf][2], oacc[mf][nf][3]);
            }
        __syncthreads();   // P/Q smem reuse across q-tiles
    }
}

// ---------------- embed + mask ----------------
__global__ void embed_kernel(const int* __restrict__ x, const float* __restrict__ emb,
                             float* __restrict__ h, __half* __restrict__ h16,
                             int* __restrict__ mask) {
    int r = blockIdx.x;
    int tok = x[r];
    if (threadIdx.x == 0) mask[r] = (tok != 0) ? 1 : 0;
    const float* e = emb + (long)tok * H_;
    float v0 = e[threadIdx.x];
    float v1 = e[threadIdx.x + 256];
    float* o = h + (long)r * H_;
    o[threadIdx.x] = v0;
    o[threadIdx.x + 256] = v1;
    __half* o16 = h16 + (long)r * H_;
    o16[threadIdx.x] = __float2half(v0);
    o16[threadIdx.x + 256] = __float2half(v1);
}

// ---------------- one-pass layernorm, 2 rows/block, fp32 or fp16 input ----------------
__global__ __launch_bounds__(512) void ln_kernel(
    const float* __restrict__ in, const __half* __restrict__ in16,
    float* __restrict__ out, __half* __restrict__ out16,
    const float* __restrict__ s, const float* __restrict__ b,
    int do_tanh) {
    __shared__ float2 red[16];
    int half = threadIdx.x >> 8;
    int t = threadIdx.x & 255;
    long r = (long)blockIdx.x * 2 + half;
    float v0, v1;
    if (in16) {
        v0 = __half2float(in16[r * H_ + t]);
        v1 = __half2float(in16[r * H_ + t + 256]);
    } else {
        v0 = in[r * H_ + t];
        v1 = in[r * H_ + t + 256];
    }
    float sa = v0 + v1;
    float sq = v0 * v0 + v1 * v1;
    int lane = threadIdx.x & 31, w = threadIdx.x >> 5;
#pragma unroll
    for (int o = 16; o; o >>= 1) {
        sa += __shfl_xor_sync(0xffffffffu, sa, o);
        sq += __shfl_xor_sync(0xffffffffu, sq, o);
    }
    if (lane == 0) red[w] = make_float2(sa, sq);
    __syncthreads();
    int base = half * 8;
    float2 tt = (lane < 8) ? red[base + lane] : make_float2(0.f, 0.f);
#pragma unroll
    for (int o = 4; o; o >>= 1) {
        tt.x += __shfl_xor_sync(0xffffffffu, tt.x, o);
        tt.y += __shfl_xor_sync(0xffffffffu, tt.y, o);
    }
    float m = __shfl_sync(0xffffffffu, tt.x, 0) * (1.f / 512.f);
    float ex2 = __shfl_sync(0xffffffffu, tt.y, 0) * (1.f / 512.f);
    float var = ex2 - m * m;
    float inv = rsqrtf(var + 1e-5f);
    float y0 = (v0 - m) * inv, y1 = (v1 - m) * inv;
    if (s) {
        y0 = y0 * s[t] + b[t];
        y1 = y1 * s[t + 256] + b[t + 256];
    }
    if (do_tanh) { y0 = tanhf(y0); y1 = tanhf(y1); }
    if (out) {
        float* o = out + r * H_;
        o[t] = y0;
        o[t + 256] = y1;
    }
    if (out16) {
        __half* o = out16 + r * H_;
        o[t] = __float2half(y0);
        o[t + 256] = __float2half(y1);
    }
}

// ---------------- parse softmax (fp16 in-place) ----------------
__device__ __forceinline__ float block_sum_8w(float v, float* red) {
    int lane = threadIdx.x & 31, w = threadIdx.x >> 5;
#pragma unroll
    for (int o = 16; o; o >>= 1) v += __shfl_xor_sync(0xffffffffu, v, o);
    if (lane == 0) red[w] = v;
    __syncthreads();
    float t = (lane < 8) ? red[lane] : 0.f;
#pragma unroll
    for (int o = 4; o; o >>= 1) t += __shfl_xor_sync(0xffffffffu, t, o);
    return __shfl_sync(0xffffffffu, t, 0);
}

__global__ void softmax_head_kernel(__half* __restrict__ head16,
                                    const int* __restrict__ mask) {
    __shared__ float red[32];
    int bi = blockIdx.x;
    int b = bi >> 8, i = bi & 255;
    __half* row = head16 + (long)bi * L_;
    int j = threadIdx.x;
    float v = (mask[b * L_ + j] != 0) ? __half2float(row[j]) * (1.f / 512.f) : -INFINITY;

    int lane = threadIdx.x & 31, w = threadIdx.x >> 5;
    float m = v;
#pragma unroll
    for (int o = 16; o; o >>= 1) m = fmaxf(m, __shfl_xor_sync(0xffffffffu, m, o));
    if (lane == 0) red[w] = m;
    __syncthreads();
    float t = (lane < 8) ? red[lane] : -INFINITY;
#pragma unroll
    for (int o = 4; o; o >>= 1) t = fmaxf(t, __shfl_xor_sync(0xffffffffu, t, o));
    m = __shfl_sync(0xffffffffu, t, 0);
    __syncthreads();

    float e = (v == -INFINITY) ? 0.f : __expf(v - m);
    float sum = block_sum_8w(e, red);
    float p = (sum > 0.f) ? e / sum : 0.f;
    if (j == i) p = 0.f;
    row[j] = __float2half(p);
}

// ---------------- head transpose (fp16) ----------------
__global__ void transpose16_kernel(const __half* __restrict__ head,
                                   __half* __restrict__ headT) {
    __shared__ __half t[32][34];
    int b = blockIdx.z;
    int i0 = blockIdx.y * 32, j0 = blockIdx.x * 32;
    const __half* src = head + (long)b * L_ * L_;
    t[threadIdx.y][threadIdx.x] = src[(long)(i0 + threadIdx.y) * L_ + j0 + threadIdx.x];
    __syncthreads();
    headT[(long)b * L_ * L_ + (long)(j0 + threadIdx.y) * L_ + i0 + threadIdx.x] =
        t[threadIdx.x][threadIdx.y];
}

// ---------------- host orchestration ----------------
#define GSM_SMALL (4 * (128 * 128 + 64 * 128))      // 98304 (4 stages)
#define GSM_BIG   (3 * (128 * 128 + 128 * 128))     // 98304 (3 stages)

static inline void launch_h(const __half* A, const __half* W, const float* bias,
                            const float* resid, float* C, __half* C16, const int* mask,
                            int M, int N, int Kd, int epilogue,
                            int conv_mode = 0, int strideA = -1, int strideW = -1,
                            int batch = 1, long sA = 0, long sB = 0, long sC = 0,
                            int force_small = 0) {
    if (strideA < 0) strideA = Kd;
    if (strideW < 0) strideW = Kd;
    if (N <= 512 || force_small) {
        dim3 g((N + 63) / 64, M / 128, batch);
        gemm_h<4, 2, 2, 4, 4><<<g, 256, GSM_SMALL>>>(A, W, bias, resid, C, C16, mask,
                                                     M, N, Kd, strideA, strideW,
                                                     sA, sB, sC, epilogue, conv_mode);
    } else {
        dim3 g((N + 127) / 128, M / 128, batch);
        gemm_h<2, 4, 4, 4, 3><<<g, 256, GSM_BIG>>>(A, W, bias, resid, C, C16, mask,
                                                   M, N, Kd, strideA, strideW,
                                                   sA, sB, sC, epilogue, conv_mode);
    }
}

extern "C" void kernel_launch(void* const* d_in, const int* in_sizes, int n_in,
                              void* d_out, int out_size) {
    const int*   x        = (const int*)d_in[0];
    const float* emb      = (const float*)d_in[2];
    const float* conv_w   = (const float*)d_in[3];
    const float* conv_b   = (const float*)d_in[4];
    const float* parent_w = (const float*)d_in[5];
    const float* parent_b = (const float*)d_in[6];
    const float* child_w  = (const float*)d_in[7];
    const float* child_b  = (const float*)d_in[8];
    const float* rel_w    = (const float*)d_in[9];
    const float* qkv_w    = (const float*)d_in[10];
    const float* qkv_b    = (const float*)d_in[11];
    const float* out_w    = (const float*)d_in[12];
    const float* out_b    = (const float*)d_in[13];
    const float* ln1_s    = (const float*)d_in[14];
    const float* ln1_b    = (const float*)d_in[15];
    const float* ln2_s    = (const float*)d_in[16];
    const float* ln2_b    = (const float*)d_in[17];
    const float* ff1_w    = (const float*)d_in[18];
    const float* ff1_b    = (const float*)d_in[19];
    const float* ff2_w    = (const float*)d_in[20];
    const float* ff2_b    = (const float*)d_in[21];
    const float* norm_s   = (const float*)d_in[22];
    const float* norm_b   = (const float*)d_in[23];
    const float* out_bias = (const float*)d_in[24];
    float* out = (float*)d_out;

    void *p;
    cudaGetSymbolAddress(&p, g_h);        float*  h       = (float*)p;
    cudaGetSymbolAddress(&p, g_pcb);      float*  pcb     = (float*)p;
    cudaGetSymbolAddress(&p, g_mask);     int*    mask    = (int*)p;
    cudaGetSymbolAddress(&p, g_head16);   __half* head16  = (__half*)p;
    cudaGetSymbolAddress(&p, g_headT16);  __half* headT16 = (__half*)p;
    cudaGetSymbolAddress(&p, g_h16);      __half* h16     = (__half*)p;
    cudaGetSymbolAddress(&p, g_hn16);     __half* hn16    = (__half*)p;
    cudaGetSymbolAddress(&p, g_pc16);     __half* pc16    = (__half*)p;
    cudaGetSymbolAddress(&p, g_qkv16);    __half* qkv16   = (__half*)p;
    cudaGetSymbolAddress(&p, g_ctx16);    __half* ctx16   = (__half*)p;
    cudaGetSymbolAddress(&p, g_ff16);     __half* ff16    = (__half*)p;
    cudaGetSymbolAddress(&p, g_convT16);  __half* convT16 = (__half*)p;
    cudaGetSymbolAddress(&p, g_qkvw16);   __half* qkvw16  = (__half*)p;
    cudaGetSymbolAddress(&p, g_outw16);   __half* outw16  = (__half*)p;
    cudaGetSymbolAddress(&p, g_ff1w16);   __half* ff1w16  = (__half*)p;
    cudaGetSymbolAddress(&p, g_ff2w16);   __half* ff2w16  = (__half*)p;
    cudaGetSymbolAddress(&p, g_pcw16);    __half* pcw16   = (__half*)p;
    cudaGetSymbolAddress(&p, g_emb16);    __half* emb16   = (__half*)p;

    cudaFuncSetAttribute(attn_mma, cudaFuncAttributeMaxDynamicSharedMemorySize, ATT_SMEM);
    cudaFuncSetAttribute(gemm_h<4, 2, 2, 4, 4>,
                         cudaFuncAttributeMaxDynamicSharedMemorySize, GSM_SMALL);
    cudaFuncSetAttribute(gemm_h<2, 4, 4, 4, 3>,
                         cudaFuncAttributeMaxDynamicSharedMemorySize, GSM_BIG);

    // ---- weight conversions ----
    convw_transpose16<<<dim3(16, 16, P_ * KW_), dim3(32, 32)>>>(conv_w, convT16);
    {
        CvtJobs j;
        j.src[0] = qkv_w;    j.dst[0] = qkvw16;           j.n4[0] = NL_ * 3 * H_ * H_ / 4;
        j.src[1] = out_w;    j.dst[1] = outw16;           j.n4[1] = NL_ * H_ * H_ / 4;
        j.src[2] = ff1_w;    j.dst[2] = ff1w16;           j.n4[2] = NL_ * DFF_ * H_ / 4;
        j.src[3] = ff2_w;    j.dst[3] = ff2w16;           j.n4[3] = NL_ * H_ * DFF_ / 4;
        j.src[4] = parent_w; j.dst[4] = pcw16;            j.n4[4] = H_ * H_ / 4;
        j.src[5] = child_w;  j.dst[5] = pcw16 + 512 * H_; j.n4[5] = H_ * H_ / 4;
        j.src[6] = emb;      j.dst[6] = emb16;            j.n4[6] = NTOK_ * H_ / 4;
        int total4 = 0;
        for (int k = 0; k < 7; k++) total4 += j.n4[k];
        cvt_multi<<<(total4 + 255) / 256, 256>>>(j, total4);
    }
    concat_bias<<<4, 256>>>(parent_b, child_b, pcb);

    // ---- embedding + mask ----
    embed_kernel<<<BL_, 256>>>(x, emb, h, h16, mask);

    // ---- parser ----
    for (int pl = 0; pl < P_; pl++) {
        launch_h(h16, convT16 + (long)pl * H_ * KW_ * H_, conv_b + pl * H_,
                 nullptr, nullptr, hn16, mask, BL_, H_, KW_ * H_, 0,
                 /*conv_mode=*/1, /*strideA=*/H_);
        ln_kernel<<<BL_ / 2, 512>>>(nullptr, hn16, nullptr, h16, nullptr, nullptr, 1);
    }

    // ---- parent+child combined GEMM ----
    launch_h(h16, pcw16, pcb, nullptr, nullptr, pc16, mask, BL_, 1024, H_, 0);

    // ---- parse logits + softmax + transpose ----
    launch_h(pc16 + 512, pc16, nullptr, nullptr, nullptr, head16, mask,
             L_, L_, H_, 0, 0, /*strideA=*/1024, /*strideW=*/1024,
             B_, (long)L_ * 1024, (long)L_ * 1024, (long)L_ * L_);
    softmax_head_kernel<<<BL_, 256>>>(head16, mask);
    transpose16_kernel<<<dim3(8, 8, B_), dim3(32, 32)>>>(head16, headT16);

    // ---- transformer ----
    for (int i = 0; i < NL_; i++) {
        ln_kernel<<<BL_ / 2, 512>>>(h, nullptr, nullptr, hn16,
                                    ln1_s + i * H_, ln1_b + i * H_, 0);
        launch_h(hn16, qkvw16 + (long)i * 3 * H_ * H_, qkv_b + i * 3 * H_,
                 nullptr, nullptr, qkv16, mask, BL_, 3 * H_, H_, 0,
                 0, -1, -1, 1, 0, 0, 0, /*force_small=*/1);
        attn_mma<<<dim3(2, NH_, B_), 256, ATT_SMEM>>>(qkv16, head16, headT16, mask,
                                                      rel_w, i, ctx16);
        launch_h(ctx16, outw16 + (long)i * H_ * H_, out_b + i * H_, h, h, nullptr, mask,
                 BL_, H_, H_, 0);
        ln_kernel<<<BL_ / 2, 512>>>(h, nullptr, nullptr, hn16,
                                    ln2_s + i * H_, ln2_b + i * H_, 0);
        launch_h(hn16, ff1w16 + (long)i * DFF_ * H_, ff1_b + i * DFF_,
                 nullptr, nullptr, ff16, mask, BL_, DFF_, H_, 1);
        launch_h(ff16, ff2w16 + (long)i * H_ * DFF_, ff2_b + i * H_, h, h, nullptr, mask,
                 BL_, H_, DFF_, 0);
    }

    // ---- final LN + tied output ----
    ln_kernel<<<BL_ / 2, 512>>>(h, nullptr, nullptr, hn16, norm_s, norm_b, 0);
    launch_h(hn16, emb16, out_bias, nullptr, out, nullptr, mask, BL_, NTOK_, H_, 0);
}

// round 14
// speedup vs baseline: 1.0073x; 1.0073x over previous
#include <cuda_runtime.h>
#include <cuda_fp16.h>
#include <math.h>
#include <stdint.h>

#define B_ 16
#define L_ 256
#define H_ 512
#define NH_ 8
#define DH_ 64
#define NL_ 6
#define NTOK_ 10000
#define P_ 4
#define KW_ 9
#define DFF_ 2048
#define BL_ (B_ * L_)

// ---------------- device scratch (fp32) ----------------
__device__ float g_h[BL_ * H_];
__device__ float g_pcb[1024];
__device__ int   g_mask[BL_];
// ---------------- device scratch (fp16) ----------------
__device__ __half g_head16[B_ * L_ * L_];
__device__ __half g_headT16[B_ * L_ * L_];
__device__ __half g_h16[BL_ * H_];
__device__ __half g_hn16[BL_ * H_];
__device__ __half g_pc16[BL_ * 1024];
__device__ __half g_qkv16[BL_ * 3 * H_];
__device__ __half g_ctx16[BL_ * H_];
__device__ __half g_ff16[BL_ * DFF_];
// fp16 weights
__device__ __half g_convT16[P_ * H_ * KW_ * H_];
__device__ __half g_qkvw16[NL_ * 3 * H_ * H_];
__device__ __half g_outw16[NL_ * H_ * H_];
__device__ __half g_ff1w16[NL_ * DFF_ * H_];
__device__ __half g_ff2w16[NL_ * H_ * DFF_];
__device__ __half g_pcw16[1024 * H_];
__device__ __half g_emb16[NTOK_ * H_];

// ================= helpers =================
__device__ __forceinline__ uint32_t pack_h2(float x, float y) {
    __half2 h = __floats2half2_rn(x, y);
    return *reinterpret_cast<uint32_t*>(&h);
}
__device__ __forceinline__ uint32_t smem_u32(const void* p) {
    uint32_t a;
    asm("{ .reg .u64 t; cvta.to.shared.u64 t, %1; cvt.u32.u64 %0, t; }" : "=r"(a) : "l"(p));
    return a;
}
__device__ __forceinline__ uint32_t sw128(uint32_t x) { return x ^ ((x >> 3) & 0x70); }

__device__ __forceinline__ void mma_f16(float c[4], uint32_t a0, uint32_t a1,
                                        uint32_t a2, uint32_t a3,
                                        uint32_t b0, uint32_t b1) {
    asm volatile(
        "mma.sync.aligned.m16n8k16.row.col.f32.f16.f16.f32 "
        "{%0,%1,%2,%3}, {%4,%5,%6,%7}, {%8,%9}, {%0,%1,%2,%3};\n"
        : "+f"(c[0]), "+f"(c[1]), "+f"(c[2]), "+f"(c[3])
        : "r"(a0), "r"(a1), "r"(a2), "r"(a3), "r"(b0), "r"(b1));
}
__device__ __forceinline__ void ldsm_x4(uint32_t& r0, uint32_t& r1, uint32_t& r2,
                                        uint32_t& r3, uint32_t addr) {
    asm volatile("ldmatrix.sync.aligned.m8n8.x4.shared.b16 {%0,%1,%2,%3}, [%4];"
                 : "=r"(r0), "=r"(r1), "=r"(r2), "=r"(r3) : "r"(addr));
}
__device__ __forceinline__ void ldsm_x4_t(uint32_t& r0, uint32_t& r1, uint32_t& r2,
                                          uint32_t& r3, uint32_t addr) {
    asm volatile("ldmatrix.sync.aligned.m8n8.x4.trans.shared.b16 {%0,%1,%2,%3}, [%4];"
                 : "=r"(r0), "=r"(r1), "=r"(r2), "=r"(r3) : "r"(addr));
}
__device__ __forceinline__ void cp16(uint32_t dst, const __half* src, int sz) {
    asm volatile("cp.async.cg.shared.global [%0], [%1], 16, %2;"
                 :: "r"(dst), "l"(__cvta_generic_to_global(src)), "r"(sz));
}

// ---------------- fused fp32 -> fp16 conversion ----------------
struct CvtJobs {
    const float* src[7];
    __half* dst[7];
    int n4[7];
};
__global__ void cvt_multi(CvtJobs j, int total4) {
    int i = blockIdx.x * 256 + threadIdx.x;
    if (i >= total4) return;
    int s = 0, base = 0;
    while (i - base >= j.n4[s]) { base += j.n4[s]; s++; }
    int o = i - base;
    float4 v = *(const float4*)(j.src[s] + (long)o * 4);
    *(uint2*)(j.dst[s] + (long)o * 4) = make_uint2(pack_h2(v.x, v.y), pack_h2(v.z, v.w));
}

// conv weights: w[p][k][ci][co] -> wt16[p][co][k*H+ci]
__global__ void convw_transpose16(const float* __restrict__ w, __half* __restrict__ wt) {
    __shared__ float t[32][33];
    int pk = blockIdx.z;
    int p = pk / KW_, k = pk % KW_;
    int ci0 = blockIdx.y * 32, co0 = blockIdx.x * 32;
    t[threadIdx.y][threadIdx.x] =
        w[((long)pk * H_ + ci0 + threadIdx.y) * H_ + co0 + threadIdx.x];
    __syncthreads();
    wt[((long)p * H_ + co0 + threadIdx.y) * (KW_ * H_) + k * H_ + ci0 + threadIdx.x] =
        __float2half(t[threadIdx.x][threadIdx.y]);
}

__global__ void concat_bias(const float* __restrict__ a, const float* __restrict__ b,
                            float* __restrict__ o) {
    int i = blockIdx.x * 256 + threadIdx.x;
    if (i < 512) o[i] = a[i];
    else if (i < 1024) o[i] = b[i - 512];
}

// =====================================================================
// fp16 GEMM: 256 threads, cp.async NS-stage, SW128 + ldmatrix, 2 CTAs/SM.
// =====================================================================
template <int WM, int WN, int MF, int NF, int NS>
__global__ __launch_bounds__(256, 2) void gemm_h(
    const __half* __restrict__ A, const __half* __restrict__ W,
    const float* __restrict__ bias, const float* __restrict__ resid,
    float* __restrict__ C, __half* __restrict__ C16,
    const int* __restrict__ cmask,
    int M, int N, int Kd, int strideA, int strideW,
    long sA, long sB, long sC,
    int epilogue, int conv_mode)
{
    constexpr int BM = WM * MF * 16;
    constexpr int BN = WN * NF * 8;
    constexpr int ABYTES = BM * 128;
    constexpr int BBYTES = BN * 128;
    constexpr int STAGEB = ABYTES + BBYTES;
    constexpr int AIT = BM * 8 / 256;
    constexpr int BIT = BN * 8 / 256;

    extern __shared__ char smem[];
    uint32_t sb = smem_u32(smem);

    int bz = blockIdx.z;
    A += (long)bz * sA;
    W += (long)bz * sB;
    if (C) C += (long)bz * sC;
    if (C16) C16 += (long)bz * sC;
    if (resid) resid += (long)bz * sC;

    const int tid = threadIdx.x;
    const int warp = tid >> 5, lane = tid & 31;
    const int wm = warp / WN;
    const int wn = warp % WN;
    const int grp = lane >> 2, tig = lane & 3;
    const int row0 = blockIdx.y * BM;
    const int col0 = blockIdx.x * BN;

    uint32_t mbits[AIT];
    if (conv_mode) {
#pragma unroll
        for (int it = 0; it < AIT; it++) {
            int r = (tid + 256 * it) >> 3;
            int arow = row0 + r;
            int bb = arow >> 8, base = arow & 255;
            uint32_t bits = 0;
#pragma unroll
            for (int s = 0; s < 9; s++) {
                int ll = base + s - 4;
                if (ll >= 0 && ll < 256 && cmask[bb * 256 + ll] != 0)
                    bits |= 1u << s;
            }
            mbits[it] = bits;
        }
    }

    float acc[MF][NF][4];
#pragma unroll
    for (int i = 0; i < MF; i++)
#pragma unroll
        for (int j = 0; j < NF; j++)
#pragma unroll
            for (int r = 0; r < 4; r++) acc[i][j][r] = 0.f;

    const int nchunks = Kd >> 6;

    auto issue = [&](int c) {
        if (c < nchunks) {
            uint32_t abase = sb + (c % NS) * STAGEB;
            uint32_t bbase = abase + ABYTES;
            const int k0 = c << 6;
#pragma unroll
            for (int it = 0; it < AIT; it++) {
                int idx = tid + 256 * it;
                int r = idx >> 3, q = idx & 7;
                int arow = row0 + r;
                const __half* src;
                int sz = 16;
                if (conv_mode) {
                    int s = c >> 3;
                    int bb = arow >> 8;
                    int ll = (arow & 255) + s - 4;
                    int lc = min(max(ll, 0), 255);
                    src = A + ((long)(bb * 256 + lc) * 512) + (k0 & 511) + q * 8;
                    sz = ((mbits[it] >> s) & 1u) ? 16 : 0;
                } else {
                    src = A + (long)arow * strideA + k0 + q * 8;
                }
                cp16(abase + sw128(r * 128 + q * 16), src, sz);
            }
#pragma unroll
            for (int it = 0; it < BIT; it++) {
                int idx = tid + 256 * it;
                int r = idx >> 3, q = idx & 7;
                int bn = col0 + r;
                int bc = min(bn, N - 1);
                int sz = (bn < N) ? 16 : 0;
                cp16(bbase + sw128(r * 128 + q * 16),
                     W + (long)bc * strideW + k0 + q * 8, sz);
            }
        }
        asm volatile("cp.async.commit_group;" ::: "memory");
    };

#pragma unroll
    for (int s = 0; s < NS - 1; s++) issue(s);

    const int arow_l = (lane & 7) + ((lane >> 3) & 1) * 8;
    const int akh = (lane >> 4) & 1;
    const int brow_l = (lane & 7) + ((lane >> 4) & 1) * 8;
    const int bkh = (lane >> 3) & 1;

    for (int c = 0; c < nchunks; c++) {
        asm volatile("cp.async.wait_group %0;" :: "n"(NS - 2) : "memory");
        __syncthreads();
        issue(c + NS - 1);

        const uint32_t Ab = sb + (c % NS) * STAGEB;
        const uint32_t Bb = Ab + ABYTES;
#pragma unroll
        for (int ks = 0; ks < 4; ks++) {
            uint32_t a[MF][4];
#pragma unroll
            for (int mf = 0; mf < MF; mf++) {
                int row = (wm * MF + mf) * 16 + arow_l;
                ldsm_x4(a[mf][0], a[mf][1], a[mf][2], a[mf][3],
                        Ab + sw128(row * 128 + ks * 32 + akh * 16));
            }
            uint32_t b[NF][2];
#pragma unroll
            for (int ng = 0; ng < NF / 2; ng++) {
                int nrow = (wn * NF + 2 * ng) * 8 + brow_l;
                uint32_t r0, r1, r2, r3;
                ldsm_x4(r0, r1, r2, r3,
                        Bb + sw128(nrow * 128 + ks * 32 + bkh * 16));
                b[2 * ng][0] = r0; b[2 * ng][1] = r1;
                b[2 * ng + 1][0] = r2; b[2 * ng + 1][1] = r3;
            }
#pragma unroll
            for (int mf = 0; mf < MF; mf++)
#pragma unroll
                for (int nf = 0; nf < NF; nf++)
                    mma_f16(acc[mf][nf], a[mf][0], a[mf][1], a[mf][2], a[mf][3],
                            b[nf][0], b[nf][1]);
        }
    }

    // ---- epilogue ----
#pragma unroll
    for (int mf = 0; mf < MF; mf++) {
        int r0 = row0 + (wm * MF + mf) * 16 + grp;
        int r1 = r0 + 8;
#pragma unroll
        for (int nf = 0; nf < NF; nf++) {
            int cb = col0 + (wn * NF + nf) * 8 + tig * 2;
            if (cb >= N) continue;
            float v0 = acc[mf][nf][0], v1 = acc[mf][nf][1];
            float v2 = acc[mf][nf][2], v3 = acc[mf][nf][3];
            if (bias) {
                float b0 = bias[cb], b1 = bias[cb + 1];
                v0 += b0; v1 += b1; v2 += b0; v3 += b1;
            }
            if (epilogue == 1) {
                v0 = (v0 > 0.f) ? v0 : 0.01f * v0;
                v1 = (v1 > 0.f) ? v1 : 0.01f * v1;
                v2 = (v2 > 0.f) ? v2 : 0.01f * v2;
                v3 = (v3 > 0.f) ? v3 : 0.01f * v3;
            }
            if (resid) {
                v0 += resid[(long)r0 * N + cb]; v1 += resid[(long)r0 * N + cb + 1];
                v2 += resid[(long)r1 * N + cb]; v3 += resid[(long)r1 * N + cb + 1];
            }
            if (C) {
                *(float2*)(C + (long)r0 * N + cb) = make_float2(v0, v1);
                *(float2*)(C + (long)r1 * N + cb) = make_float2(v2, v3);
            }
            if (C16) {
                *(__half2*)(C16 + (long)r0 * N + cb) = __floats2half2_rn(v0, v1);
                *(__half2*)(C16 + (long)r1 * N + cb) = __floats2half2_rn(v2, v3);
            }
        }
    }
}

// =====================================================================
// tensor-core attention: 2 q-tiles (128 rows) per CTA, K/V resident.
// =====================================================================
#define ATT_SM_Q 0
#define ATT_SM_K 8192
#define ATT_SM_V 40960
#define ATT_SM_P 73728
#define ATT_SM_RED 106496
#define ATT_SMEM (106496 + 2048)

__device__ __forceinline__ uint32_t swp(int r, int c2) {
    return (uint32_t)(r * 512 + (c2 ^ ((r & 7) << 4)));
}

__global__ __launch_bounds__(256) void attn_mma(
    const __half* __restrict__ qkv, const __half* __restrict__ head,
    const __half* __restrict__ headT, const int* __restrict__ mask,
    const float* __restrict__ relw, int layer, __half* __restrict__ ctx)
{
    extern __shared__ char sma[];
    uint32_t sbase = smem_u32(sma);
    const int b = blockIdx.z, hh = blockIdx.y;
    const int tid = threadIdx.x, warp = tid >> 5, lane = tid & 31;
    const int wm = warp >> 2, wn = warp & 3;
    const int r4 = lane >> 2, c2 = (lane & 3) * 2;

    const __half* qb = qkv + (long)b * L_ * 1536 + hh * 64;
    const __half* kb = qb + 512;
    const __half* vb = qb + 1024;

    for (int idx = tid; idx < 256 * 8; idx += 256) {
        int r = idx >> 3, q = idx & 7;
        cp16(sbase + ATT_SM_K + sw128(r * 128 + q * 16), kb + (long)r * 1536 + q * 8, 16);
        cp16(sbase + ATT_SM_V + sw128(r * 128 + q * 16), vb + (long)r * 1536 + q * 8, 16);
    }

    float w0, w1;
    {
        float a0v = relw[(layer * NH_ + hh) * 2 + 0];
        float a1v = relw[(layer * NH_ + hh) * 2 + 1];
        float mv = fmaxf(a0v, a1v);
        float e0 = __expf(a0v - mv), e1 = __expf(a1v - mv);
        w0 = e0 / (e0 + e1); w1 = e1 / (e0 + e1);
    }

    for (int tq = 0; tq < 2; tq++) {
        const int i0 = blockIdx.x * 128 + tq * 64;

        for (int idx = tid; idx < 64 * 8; idx += 256) {
            int r = idx >> 3, q = idx & 7;
            cp16(sbase + ATT_SM_Q + sw128(r * 128 + q * 16),
                 qb + (long)(i0 + r) * 1536 + q * 8, 16);
        }
        asm volatile("cp.async.commit_group;" ::: "memory");
        asm volatile("cp.async.wait_group 0;" ::: "memory");
        __syncthreads();

        float acc[2][8][4];
#pragma unroll
        for (int i = 0; i < 2; i++)
#pragma unroll
            for (int j = 0; j < 8; j++)
#pragma unroll
                for (int r = 0; r < 4; r++) acc[i][j][r] = 0.f;

#pragma unroll
        for (int kk = 0; kk < 4; kk++) {
            uint32_t a[2][4];
#pragma unroll
            for (int mf = 0; mf < 2; mf++) {
                int row = wm * 32 + mf * 16 + (lane & 7) + ((lane >> 3) & 1) * 8;
                int kh = (lane >> 4) & 1;
                ldsm_x4(a[mf][0], a[mf][1], a[mf][2], a[mf][3],
                        sbase + ATT_SM_Q + sw128(row * 128 + kk * 32 + kh * 16));
            }
            uint32_t bf[8][2];
#pragma unroll
            for (int ng = 0; ng < 4; ng++) {
                int nrow = wn * 64 + ng * 16 + (lane & 7) + ((lane >> 4) & 1) * 8;
                int kh = (lane >> 3) & 1;
                uint32_t r0, r1, r2, r3;
                ldsm_x4(r0, r1, r2, r3,
                        sbase + ATT_SM_K + sw128(nrow * 128 + kk * 32 + kh * 16));
                bf[2 * ng][0] = r0; bf[2 * ng][1] = r1;
                bf[2 * ng + 1][0] = r2; bf[2 * ng + 1][1] = r3;
            }
#pragma unroll
            for (int mf = 0; mf < 2; mf++)
#pragma unroll
                for (int nf = 0; nf < 8; nf++)
                    mma_f16(acc[mf][nf], a[mf][0], a[mf][1], a[mf][2], a[mf][3],
                            bf[nf][0], bf[nf][1]);
        }

#pragma unroll
        for (int nf = 0; nf < 8; nf++) {
            int j = wn * 64 + nf * 8 + c2;
            int m0 = mask[b * L_ + j], m1 = mask[b * L_ + j + 1];
#pragma unroll
            for (int mf = 0; mf < 2; mf++) {
                int ia = i0 + wm * 32 + mf * 16 + r4;
                float2 hd = __half22float2(*(const __half2*)(head + ((long)(b * L_ + ia)) * L_ + j));
                float2 ht = __half22float2(*(const __half2*)(headT + ((long)(b * L_ + ia)) * L_ + j));
                float s0 = acc[mf][nf][0] * 0.125f + w0 * hd.x + w1 * ht.x;
                float s1 = acc[mf][nf][1] * 0.125f + w0 * hd.y + w1 * ht.y;
                acc[mf][nf][0] = m0 ? s0 : -1e30f;
                acc[mf][nf][1] = m1 ? s1 : -1e30f;
                int ib = ia + 8;
                float2 hd2 = __half22float2(*(const __half2*)(head + ((long)(b * L_ + ib)) * L_ + j));
                float2 ht2 = __half22float2(*(const __half2*)(headT + ((long)(b * L_ + ib)) * L_ + j));
                float s2 = acc[mf][nf][2] * 0.125f + w0 * hd2.x + w1 * ht2.x;
                float s3 = acc[mf][nf][3] * 0.125f + w0 * hd2.y + w1 * ht2.y;
                acc[mf][nf][2] = m0 ? s2 : -1e30f;
                acc[mf][nf][3] = m1 ? s3 : -1e30f;
            }
        }

        float* redm = (float*)(sma + ATT_SM_RED);
        float* reds = redm + 256;
        float mx[4];
#pragma unroll
        for (int mf = 0; mf < 2; mf++)
#pragma unroll
            for (int hf = 0; hf < 2; hf++) {
                float m = -1e30f;
#pragma unroll
                for (int nf = 0; nf < 8; nf++)
                    m = fmaxf(m, fmaxf(acc[mf][nf][2 * hf], acc[mf][nf][2 * hf + 1]));
                mx[mf * 2 + hf] = m;
            }
#pragma unroll
        for (int ri = 0; ri < 4; ri++) {
            mx[ri] = fmaxf(mx[ri], __shfl_xor_sync(0xffffffffu, mx[ri], 1));
            mx[ri] = fmaxf(mx[ri], __shfl_xor_sync(0xffffffffu, mx[ri], 2));
        }
        if ((lane & 3) == 0) {
#pragma unroll
            for (int mf = 0; mf < 2; mf++)
#pragma unroll
                for (int hf = 0; hf < 2; hf++)
                    redm[wn * 64 + wm * 32 + mf * 16 + hf * 8 + r4] = mx[mf * 2 + hf];
        }
        __syncthreads();
        float MX[4];
#pragma unroll
        for (int mf = 0; mf < 2; mf++)
#pragma unroll
            for (int hf = 0; hf < 2; hf++) {
                int row = wm * 32 + mf * 16 + hf * 8 + r4;
                float m = redm[row];
                m = fmaxf(m, redm[64 + row]);
                m = fmaxf(m, redm[128 + row]);
                m = fmaxf(m, redm[192 + row]);
                MX[mf * 2 + hf] = m;
            }
        float sm[4] = {0.f, 0.f, 0.f, 0.f};
#pragma unroll
        for (int mf = 0; mf < 2; mf++)
#pragma unroll
            for (int nf = 0; nf < 8; nf++)
#pragma unroll
                for (int hf = 0; hf < 2; hf++) {
                    float e0 = __expf(acc[mf][nf][2 * hf] - MX[mf * 2 + hf]);
                    float e1 = __expf(acc[mf][nf][2 * hf + 1] - MX[mf * 2 + hf]);
                    acc[mf][nf][2 * hf] = e0;
                    acc[mf][nf][2 * hf + 1] = e1;
                    sm[mf * 2 + hf] += e0 + e1;
                }
#pragma unroll
        for (int ri = 0; ri < 4; ri++) {
            sm[ri] += __shfl_xor_sync(0xffffffffu, sm[ri], 1);
            sm[ri] += __shfl_xor_sync(0xffffffffu, sm[ri], 2);
        }
        if ((lane & 3) == 0) {
#pragma unroll
            for (int mf = 0; mf < 2; mf++)
#pragma unroll
                for (int hf = 0; hf < 2; hf++)
                    reds[wn * 64 + wm * 32 + mf * 16 + hf * 8 + r4] = sm[mf * 2 + hf];
        }
        __syncthreads();
        float inv[4];
#pragma unroll
        for (int mf = 0; mf < 2; mf++)
#pragma unroll
            for (int hf = 0; hf < 2; hf++) {
                int row = wm * 32 + mf * 16 + hf * 8 + r4;
                float t = reds[row] + reds[64 + row] + reds[128 + row] + reds[192 + row];
                inv[mf * 2 + hf] = 1.f / t;
            }

#pragma unroll
        for (int mf = 0; mf < 2; mf++)
#pragma unroll
            for (int nf = 0; nf < 8; nf++) {
                int rowa = wm * 32 + mf * 16 + r4;
                int j = wn * 64 + nf * 8 + c2;
                *(uint32_t*)(sma + ATT_SM_P + swp(rowa, j * 2)) =
                    pack_h2(acc[mf][nf][0] * inv[mf * 2], acc[mf][nf][1] * inv[mf * 2]);
                *(uint32_t*)(sma + ATT_SM_P + swp(rowa + 8, j * 2)) =
                    pack_h2(acc[mf][nf][2] * inv[mf * 2 + 1], acc[mf][nf][3] * inv[mf * 2 + 1]);
            }
        __syncthreads();

        float oacc[2][2][4];
#pragma unroll
        for (int i = 0; i < 2; i++)
#pragma unroll
            for (int j = 0; j < 2; j++)
#pragma unroll
                for (int r = 0; r < 4; r++) oacc[i][j][r] = 0.f;

#pragma unroll
        for (int kk = 0; kk < 16; kk++) {
            uint32_t a[2][4];
#pragma unroll
            for (int mf = 0; mf < 2; mf++) {
                int row = wm * 32 + mf * 16 + (lane & 7) + ((lane >> 3) & 1) * 8;
                int kh = (lane >> 4) & 1;
                ldsm_x4(a[mf][0], a[mf][1], a[mf][2], a[mf][3],
                        sbase + ATT_SM_P + swp(row, kk * 32 + kh * 16));
            }
            uint32_t bf[2][2];
            {
                int kvrow = kk * 16 + (lane & 7) + ((lane >> 3) & 1) * 8;
                int nb = wn * 16 + ((lane >> 4) & 1) * 8;
                uint32_t r0, r1, r2, r3;
                ldsm_x4_t(r0, r1, r2, r3,
                          sbase + ATT_SM_V + sw128(kvrow * 128 + nb * 2));
                bf[0][0] = r0; bf[0][1] = r1; bf[1][0] = r2; bf[1][1] = r3;
            }
#pragma unroll
            for (int mf = 0; mf < 2; mf++)
#pragma unroll
                for (int nf = 0; nf < 2; nf++)
                    mma_f16(oacc[mf][nf], a[mf][0], a[mf][1], a[mf][2], a[mf][3],
                            bf[nf][0], bf[nf][1]);
        }

#pragma unroll
        for (int mf = 0; mf < 2; mf++)
#pragma unroll
            for (int nf = 0; nf < 2; nf++) {
                int row = i0 + wm * 32 + mf * 16 + r4;
                int d = wn * 16 + nf * 8 + c2;
                __half* dst = ctx + ((long)(b * L_) + row) * H_ + hh * 64 + d;
                *(__half2*)dst = __floats2half2_rn(oacc[mf][nf][0], oacc[mf][nf][1]);
                *(__half2*)(dst + 8 * H_) = __floats2half2_rn(oacc[mf][nf][2], oacc[mf][nf][3]);
            }
        __syncthreads();
    }
}

// ---------------- embed + mask ----------------
__global__ void embed_kernel(const int* __restrict__ x, const float* __restrict__ emb,
                             float* __restrict__ h, __half* __restrict__ h16,
                             int* __restrict__ mask) {
    int r = blockIdx.x;
    int tok = x[r];
    if (threadIdx.x == 0) mask[r] = (tok != 0) ? 1 : 0;
    const float* e = emb + (long)tok * H_;
    float v0 = e[threadIdx.x];
    float v1 = e[threadIdx.x + 256];
    float* o = h + (long)r * H_;
    o[threadIdx.x] = v0;
    o[threadIdx.x + 256] = v1;
    __half* o16 = h16 + (long)r * H_;
    o16[threadIdx.x] = __float2half(v0);
    o16[threadIdx.x + 256] = __float2half(v1);
}

// ---------------- one-pass layernorm, 2 rows/block, fp32 or fp16 input ----------------
__global__ __launch_bounds__(512) void ln_kernel(
    const float* __restrict__ in, const __half* __restrict__ in16,
    float* __restrict__ out, __half* __restrict__ out16,
    const float* __restrict__ s, const float* __restrict__ b,
    int do_tanh) {
    __shared__ float2 red[16];
    int half = threadIdx.x >> 8;
    int t = threadIdx.x & 255;
    long r = (long)blockIdx.x * 2 + half;
    float v0, v1;
    if (in16) {
        v0 = __half2float(in16[r * H_ + t]);
        v1 = __half2float(in16[r * H_ + t + 256]);
    } else {
        v0 = in[r * H_ + t];
        v1 = in[r * H_ + t + 256];
    }
    float sa = v0 + v1;
    float sq = v0 * v0 + v1 * v1;
    int lane = threadIdx.x & 31, w = threadIdx.x >> 5;
#pragma unroll
    for (int o = 16; o; o >>= 1) {
        sa += __shfl_xor_sync(0xffffffffu, sa, o);
        sq += __shfl_xor_sync(0xffffffffu, sq, o);
    }
    if (lane == 0) red[w] = make_float2(sa, sq);
    __syncthreads();
    int base = half * 8;
    float2 tt = (lane < 8) ? red[base + lane] : make_float2(0.f, 0.f);
#pragma unroll
    for (int o = 4; o; o >>= 1) {
        tt.x += __shfl_xor_sync(0xffffffffu, tt.x, o);
        tt.y += __shfl_xor_sync(0xffffffffu, tt.y, o);
    }
    float m = __shfl_sync(0xffffffffu, tt.x, 0) * (1.f / 512.f);
    float ex2 = __shfl_sync(0xffffffffu, tt.y, 0) * (1.f / 512.f);
    float var = ex2 - m * m;
    float inv = rsqrtf(var + 1e-5f);
    float y0 = (v0 - m) * inv, y1 = (v1 - m) * inv;
    if (s) {
        y0 = y0 * s[t] + b[t];
        y1 = y1 * s[t + 256] + b[t + 256];
    }
    if (do_tanh) { y0 = tanhf(y0); y1 = tanhf(y1); }
    if (out) {
        float* o = out + r * H_;
        o[t] = y0;
        o[t + 256] = y1;
    }
    if (out16) {
        __half* o = out16 + r * H_;
        o[t] = __float2half(y0);
        o[t + 256] = __float2half(y1);
    }
}

// ---------------- parse softmax (fp16 in-place) ----------------
__device__ __forceinline__ float block_sum_8w(float v, float* red) {
    int lane = threadIdx.x & 31, w = threadIdx.x >> 5;
#pragma unroll
    for (int o = 16; o; o >>= 1) v += __shfl_xor_sync(0xffffffffu, v, o);
    if (lane == 0) red[w] = v;
    __syncthreads();
    float t = (lane < 8) ? red[lane] : 0.f;
#pragma unroll
    for (int o = 4; o; o >>= 1) t += __shfl_xor_sync(0xffffffffu, t, o);
    return __shfl_sync(0xffffffffu, t, 0);
}

__global__ void softmax_head_kernel(__half* __restrict__ head16,
                                    const int* __restrict__ mask) {
    __shared__ float red[32];
    int bi = blockIdx.x;
    int b = bi >> 8, i = bi & 255;
    __half* row = head16 + (long)bi * L_;
    int j = threadIdx.x;
    float v = (mask[b * L_ + j] != 0) ? __half2float(row[j]) * (1.f / 512.f) : -INFINITY;

    int lane = threadIdx.x & 31, w = threadIdx.x >> 5;
    float m = v;
#pragma unroll
    for (int o = 16; o; o >>= 1) m = fmaxf(m, __shfl_xor_sync(0xffffffffu, m, o));
    if (lane == 0) red[w] = m;
    __syncthreads();
    float t = (lane < 8) ? red[lane] : -INFINITY;
#pragma unroll
    for (int o = 4; o; o >>= 1) t = fmaxf(t, __shfl_xor_sync(0xffffffffu, t, o));
    m = __shfl_sync(0xffffffffu, t, 0);
    __syncthreads();

    float e = (v == -INFINITY) ? 0.f : __expf(v - m);
    float sum = block_sum_8w(e, red);
    float p = (sum > 0.f) ? e / sum : 0.f;
    if (j == i) p = 0.f;
    row[j] = __float2half(p);
}

// ---------------- head transpose (fp16) ----------------
__global__ void transpose16_kernel(const __half* __restrict__ head,
                                   __half* __restrict__ headT) {
    __shared__ __half t[32][34];
    int b = blockIdx.z;
    int i0 = blockIdx.y * 32, j0 = blockIdx.x * 32;
    const __half* src = head + (long)b * L_ * L_;
    t[threadIdx.y][threadIdx.x] = src[(long)(i0 + threadIdx.y) * L_ + j0 + threadIdx.x];
    __syncthreads();
    headT[(long)b * L_ * L_ + (long)(j0 + threadIdx.y) * L_ + i0 + threadIdx.x] =
        t[threadIdx.x][threadIdx.y];
}

// ---------------- host orchestration ----------------
#define GSM_SMALL (4 * (128 * 128 + 64 * 128))      // 98304 (4 stages)
#define GSM_BIG   (3 * (128 * 128 + 128 * 128))     // 98304 (3 stages)

static inline void launch_h(const __half* A, const __half* W, const float* bias,
                            const float* resid, float* C, __half* C16, const int* mask,
                            int M, int N, int Kd, int epilogue,
                            int conv_mode = 0, int strideA = -1, int strideW = -1,
                            int batch = 1, long sA = 0, long sB = 0, long sC = 0) {
    if (strideA < 0) strideA = Kd;
    if (strideW < 0) strideW = Kd;
    if (N <= 512) {
        dim3 g((N + 63) / 64, M / 128, batch);
        gemm_h<4, 2, 2, 4, 4><<<g, 256, GSM_SMALL>>>(A, W, bias, resid, C, C16, mask,
                                                     M, N, Kd, strideA, strideW,
                                                     sA, sB, sC, epilogue, conv_mode);
    } else {
        dim3 g((N + 127) / 128, M / 128, batch);
        gemm_h<2, 4, 4, 4, 3><<<g, 256, GSM_BIG>>>(A, W, bias, resid, C, C16, mask,
                                                   M, N, Kd, strideA, strideW,
                                                   sA, sB, sC, epilogue, conv_mode);
    }
}

extern "C" void kernel_launch(void* const* d_in, const int* in_sizes, int n_in,
                              void* d_out, int out_size) {
    const int*   x        = (const int*)d_in[0];
    const float* emb      = (const float*)d_in[2];
    const float* conv_w   = (const float*)d_in[3];
    const float* conv_b   = (const float*)d_in[4];
    const float* parent_w = (const float*)d_in[5];
    const float* parent_b = (const float*)d_in[6];
    const float* child_w  = (const float*)d_in[7];
    const float* child_b  = (const float*)d_in[8];
    const float* rel_w    = (const float*)d_in[9];
    const float* qkv_w    = (const float*)d_in[10];
    const float* qkv_b    = (const float*)d_in[11];
    const float* out_w    = (const float*)d_in[12];
    const float* out_b    = (const float*)d_in[13];
    const float* ln1_s    = (const float*)d_in[14];
    const float* ln1_b    = (const float*)d_in[15];
    const float* ln2_s    = (const float*)d_in[16];
    const float* ln2_b    = (const float*)d_in[17];
    const float* ff1_w    = (const float*)d_in[18];
    const float* ff1_b    = (const float*)d_in[19];
    const float* ff2_w    = (const float*)d_in[20];
    const float* ff2_b    = (const float*)d_in[21];
    const float* norm_s   = (const float*)d_in[22];
    const float* norm_b   = (const float*)d_in[23];
    const float* out_bias = (const float*)d_in[24];
    float* out = (float*)d_out;

    void *p;
    cudaGetSymbolAddress(&p, g_h);        float*  h       = (float*)p;
    cudaGetSymbolAddress(&p, g_pcb);      float*  pcb     = (float*)p;
    cudaGetSymbolAddress(&p, g_mask);     int*    mask    = (int*)p;
    cudaGetSymbolAddress(&p, g_head16);   __half* head16  = (__half*)p;
    cudaGetSymbolAddress(&p, g_headT16);  __half* headT16 = (__half*)p;
    cudaGetSymbolAddress(&p, g_h16);      __half* h16     = (__half*)p;
    cudaGetSymbolAddress(&p, g_hn16);     __half* hn16    = (__half*)p;
    cudaGetSymbolAddress(&p, g_pc16);     __half* pc16    = (__half*)p;
    cudaGetSymbolAddress(&p, g_qkv16);    __half* qkv16   = (__half*)p;
    cudaGetSymbolAddress(&p, g_ctx16);    __half* ctx16   = (__half*)p;
    cudaGetSymbolAddress(&p, g_ff16);     __half* ff16    = (__half*)p;
    cudaGetSymbolAddress(&p, g_convT16);  __half* convT16 = (__half*)p;
    cudaGetSymbolAddress(&p, g_qkvw16);   __half* qkvw16  = (__half*)p;
    cudaGetSymbolAddress(&p, g_outw16);   __half* outw16  = (__half*)p;
    cudaGetSymbolAddress(&p, g_ff1w16);   __half* ff1w16  = (__half*)p;
    cudaGetSymbolAddress(&p, g_ff2w16);   __half* ff2w16  = (__half*)p;
    cudaGetSymbolAddress(&p, g_pcw16);    __half* pcw16   = (__half*)p;
    cudaGetSymbolAddress(&p, g_emb16);    __half* emb16   = (__half*)p;

    cudaFuncSetAttribute(attn_mma, cudaFuncAttributeMaxDynamicSharedMemorySize, ATT_SMEM);
    cudaFuncSetAttribute(gemm_h<4, 2, 2, 4, 4>,
                         cudaFuncAttributeMaxDynamicSharedMemorySize, GSM_SMALL);
    cudaFuncSetAttribute(gemm_h<2, 4, 4, 4, 3>,
                         cudaFuncAttributeMaxDynamicSharedMemorySize, GSM_BIG);

    // ---- weight conversions ----
    convw_transpose16<<<dim3(16, 16, P_ * KW_), dim3(32, 32)>>>(conv_w, convT16);
    {
        CvtJobs j;
        j.src[0] = qkv_w;    j.dst[0] = qkvw16;           j.n4[0] = NL_ * 3 * H_ * H_ / 4;
        j.src[1] = out_w;    j.dst[1] = outw16;           j.n4[1] = NL_ * H_ * H_ / 4;
        j.src[2] = ff1_w;    j.dst[2] = ff1w16;           j.n4[2] = NL_ * DFF_ * H_ / 4;
        j.src[3] = ff2_w;    j.dst[3] = ff2w16;           j.n4[3] = NL_ * H_ * DFF_ / 4;
        j.src[4] = parent_w; j.dst[4] = pcw16;            j.n4[4] = H_ * H_ / 4;
        j.src[5] = child_w;  j.dst[5] = pcw16 + 512 * H_; j.n4[5] = H_ * H_ / 4;
        j.src[6] = emb;      j.dst[6] = emb16;            j.n4[6] = NTOK_ * H_ / 4;
        int total4 = 0;
        for (int k = 0; k < 7; k++) total4 += j.n4[k];
        cvt_multi<<<(total4 + 255) / 256, 256>>>(j, total4);
    }
    concat_bias<<<4, 256>>>(parent_b, child_b, pcb);

    // ---- embedding + mask ----
    embed_kernel<<<BL_, 256>>>(x, emb, h, h16, mask);

    // ---- parser ----
    for (int pl = 0; pl < P_; pl++) {
        launch_h(h16, convT16 + (long)pl * H_ * KW_ * H_, conv_b + pl * H_,
                 nullptr, nullptr, hn16, mask, BL_, H_, KW_ * H_, 0,
                 /*conv_mode=*/1, /*strideA=*/H_);
        ln_kernel<<<BL_ / 2, 512>>>(nullptr, hn16, nullptr, h16, nullptr, nullptr, 1);
    }

    // ---- parent+child combined GEMM ----
    launch_h(h16, pcw16, pcb, nullptr, nullptr, pc16, mask, BL_, 1024, H_, 0);

    // ---- parse logits + softmax + transpose ----
    launch_h(pc16 + 512, pc16, nullptr, nullptr, nullptr, head16, mask,
             L_, L_, H_, 0, 0, /*strideA=*/1024, /*strideW=*/1024,
             B_, (long)L_ * 1024, (long)L_ * 1024, (long)L_ * L_);
    softmax_head_kernel<<<BL_, 256>>>(head16, mask);
    transpose16_kernel<<<dim3(8, 8, B_), dim3(32, 32)>>>(head16, headT16);

    // ---- transformer ----
    for (int i = 0; i < NL_; i++) {
        ln_kernel<<<BL_ / 2, 512>>>(h, nullptr, nullptr, hn16,
                                    ln1_s + i * H_, ln1_b + i * H_, 0);
        launch_h(hn16, qkvw16 + (long)i * 3 * H_ * H_, qkv_b + i * 3 * H_,
                 nullptr, nullptr, qkv16, mask, BL_, 3 * H_, H_, 0);
        attn_mma<<<dim3(2, NH_, B_), 256, ATT_SMEM>>>(qkv16, head16, headT16, mask,
                                                      rel_w, i, ctx16);
        launch_h(ctx16, outw16 + (long)i * H_ * H_, out_b + i * H_, h, h, nullptr, mask,
                 BL_, H_, H_, 0);
        ln_kernel<<<BL_ / 2, 512>>>(h, nullptr, nullptr, hn16,
                                    ln2_s + i * H_, ln2_b + i * H_, 0);
        launch_h(hn16, ff1w16 + (long)i * DFF_ * H_, ff1_b + i * DFF_,
                 nullptr, nullptr, ff16, mask, BL_, DFF_, H_, 1);
        launch_h(ff16, ff2w16 + (long)i * H_ * DFF_, ff2_b + i * H_, h, h, nullptr, mask,
                 BL_, H_, DFF_, 0);
    }

    // ---- final LN + tied output ----
    ln_kernel<<<BL_ / 2, 512>>>(h, nullptr, nullptr, hn16, norm_s, norm_b, 0);
    launch_h(hn16, emb16, out_bias, nullptr, out, nullptr, mask, BL_, NTOK_, H_, 0);
}

// round 15
// speedup vs baseline: 1.0454x; 1.0379x over previous
#include <cuda_runtime.h>
#include <cuda_fp16.h>
#include <math.h>
#include <stdint.h>

#define B_ 16
#define L_ 256
#define H_ 512
#define NH_ 8
#define DH_ 64
#define NL_ 6
#define NTOK_ 10000
#define P_ 4
#define KW_ 9
#define DFF_ 2048
#define BL_ (B_ * L_)

// ---------------- device scratch (fp32) ----------------
__device__ float g_h[BL_ * H_];
__device__ float g_pcb[1024];
__device__ int   g_mask[BL_];
// ---------------- device scratch (fp16) ----------------
__device__ __half g_head16[B_ * L_ * L_];
__device__ __half g_headT16[B_ * L_ * L_];
__device__ __half g_h16[BL_ * H_];
__device__ __half g_hn16[BL_ * H_];
__device__ __half g_pc16[BL_ * 1024];
__device__ __half g_qkv16[BL_ * 3 * H_];
__device__ __half g_ctx16[BL_ * H_];
__device__ __half g_ff16[BL_ * DFF_];
// fp16 weights
__device__ __half g_convT16[P_ * H_ * KW_ * H_];
__device__ __half g_qkvw16[NL_ * 3 * H_ * H_];
__device__ __half g_outw16[NL_ * H_ * H_];
__device__ __half g_ff1w16[NL_ * DFF_ * H_];
__device__ __half g_ff2w16[NL_ * H_ * DFF_];
__device__ __half g_pcw16[1024 * H_];
__device__ __half g_emb16[NTOK_ * H_];

// ================= helpers =================
__device__ __forceinline__ uint32_t pack_h2(float x, float y) {
    __half2 h = __floats2half2_rn(x, y);
    return *reinterpret_cast<uint32_t*>(&h);
}
__device__ __forceinline__ uint32_t smem_u32(const void* p) {
    uint32_t a;
    asm("{ .reg .u64 t; cvta.to.shared.u64 t, %1; cvt.u32.u64 %0, t; }" : "=r"(a) : "l"(p));
    return a;
}
__device__ __forceinline__ uint32_t sw128(uint32_t x) { return x ^ ((x >> 3) & 0x70); }

__device__ __forceinline__ void mma_f16(float c[4], uint32_t a0, uint32_t a1,
                                        uint32_t a2, uint32_t a3,
                                        uint32_t b0, uint32_t b1) {
    asm volatile(
        "mma.sync.aligned.m16n8k16.row.col.f32.f16.f16.f32 "
        "{%0,%1,%2,%3}, {%4,%5,%6,%7}, {%8,%9}, {%0,%1,%2,%3};\n"
        : "+f"(c[0]), "+f"(c[1]), "+f"(c[2]), "+f"(c[3])
        : "r"(a0), "r"(a1), "r"(a2), "r"(a3), "r"(b0), "r"(b1));
}
__device__ __forceinline__ void ldsm_x4(uint32_t& r0, uint32_t& r1, uint32_t& r2,
                                        uint32_t& r3, uint32_t addr) {
    asm volatile("ldmatrix.sync.aligned.m8n8.x4.shared.b16 {%0,%1,%2,%3}, [%4];"
                 : "=r"(r0), "=r"(r1), "=r"(r2), "=r"(r3) : "r"(addr));
}
__device__ __forceinline__ void ldsm_x4_t(uint32_t& r0, uint32_t& r1, uint32_t& r2,
                                          uint32_t& r3, uint32_t addr) {
    asm volatile("ldmatrix.sync.aligned.m8n8.x4.trans.shared.b16 {%0,%1,%2,%3}, [%4];"
                 : "=r"(r0), "=r"(r1), "=r"(r2), "=r"(r3) : "r"(addr));
}
__device__ __forceinline__ void cp16(uint32_t dst, const __half* src, int sz) {
    asm volatile("cp.async.cg.shared.global [%0], [%1], 16, %2;"
                 :: "r"(dst), "l"(__cvta_generic_to_global(src)), "r"(sz));
}

// ---------------- fused fp32 -> fp16 conversion ----------------
struct CvtJobs {
    const float* src[7];
    __half* dst[7];
    int n4[7];
};
__global__ void cvt_multi(CvtJobs j, int total4) {
    int i = blockIdx.x * 256 + threadIdx.x;
    if (i >= total4) return;
    int s = 0, base = 0;
    while (i - base >= j.n4[s]) { base += j.n4[s]; s++; }
    int o = i - base;
    float4 v = *(const float4*)(j.src[s] + (long)o * 4);
    *(uint2*)(j.dst[s] + (long)o * 4) = make_uint2(pack_h2(v.x, v.y), pack_h2(v.z, v.w));
}

// conv weights: w[p][k][ci][co] -> wt16[p][co][k*H+ci]
__global__ void convw_transpose16(const float* __restrict__ w, __half* __restrict__ wt) {
    __shared__ float t[32][33];
    int pk = blockIdx.z;
    int p = pk / KW_, k = pk % KW_;
    int ci0 = blockIdx.y * 32, co0 = blockIdx.x * 32;
    t[threadIdx.y][threadIdx.x] =
        w[((long)pk * H_ + ci0 + threadIdx.y) * H_ + co0 + threadIdx.x];
    __syncthreads();
    wt[((long)p * H_ + co0 + threadIdx.y) * (KW_ * H_) + k * H_ + ci0 + threadIdx.x] =
        __float2half(t[threadIdx.x][threadIdx.y]);
}

__global__ void concat_bias(const float* __restrict__ a, const float* __restrict__ b,
                            float* __restrict__ o) {
    int i = blockIdx.x * 256 + threadIdx.x;
    if (i < 512) o[i] = a[i];
    else if (i < 1024) o[i] = b[i - 512];
}

// =====================================================================
// fp16 GEMM: 256 threads, cp.async NS-stage, SW128 + ldmatrix, 2 CTAs/SM.
// =====================================================================
template <int WM, int WN, int MF, int NF, int NS>
__global__ __launch_bounds__(256, 2) void gemm_h(
    const __half* __restrict__ A, const __half* __restrict__ W,
    const float* __restrict__ bias, const float* __restrict__ resid,
    float* __restrict__ C, __half* __restrict__ C16,
    const int* __restrict__ cmask,
    int M, int N, int Kd, int strideA, int strideW,
    long sA, long sB, long sC,
    int epilogue, int conv_mode)
{
    constexpr int BM = WM * MF * 16;
    constexpr int BN = WN * NF * 8;
    constexpr int ABYTES = BM * 128;
    constexpr int BBYTES = BN * 128;
    constexpr int STAGEB = ABYTES + BBYTES;
    constexpr int AIT = BM * 8 / 256;
    constexpr int BIT = BN * 8 / 256;

    extern __shared__ char smem[];
    uint32_t sb = smem_u32(smem);

    int bz = blockIdx.z;
    A += (long)bz * sA;
    W += (long)bz * sB;
    if (C) C += (long)bz * sC;
    if (C16) C16 += (long)bz * sC;
    if (resid) resid += (long)bz * sC;

    const int tid = threadIdx.x;
    const int warp = tid >> 5, lane = tid & 31;
    const int wm = warp / WN;
    const int wn = warp % WN;
    const int grp = lane >> 2, tig = lane & 3;
    const int row0 = blockIdx.y * BM;
    const int col0 = blockIdx.x * BN;

    uint32_t mbits[AIT];
    if (conv_mode) {
#pragma unroll
        for (int it = 0; it < AIT; it++) {
            int r = (tid + 256 * it) >> 3;
            int arow = row0 + r;
            int bb = arow >> 8, base = arow & 255;
            uint32_t bits = 0;
#pragma unroll
            for (int s = 0; s < 9; s++) {
                int ll = base + s - 4;
                if (ll >= 0 && ll < 256 && cmask[bb * 256 + ll] != 0)
                    bits |= 1u << s;
            }
            mbits[it] = bits;
        }
    }

    float acc[MF][NF][4];
#pragma unroll
    for (int i = 0; i < MF; i++)
#pragma unroll
        for (int j = 0; j < NF; j++)
#pragma unroll
            for (int r = 0; r < 4; r++) acc[i][j][r] = 0.f;

    const int nchunks = Kd >> 6;

    auto issue = [&](int c) {
        if (c < nchunks) {
            uint32_t abase = sb + (c % NS) * STAGEB;
            uint32_t bbase = abase + ABYTES;
            const int k0 = c << 6;
#pragma unroll
            for (int it = 0; it < AIT; it++) {
                int idx = tid + 256 * it;
                int r = idx >> 3, q = idx & 7;
                int arow = row0 + r;
                const __half* src;
                int sz = 16;
                if (conv_mode) {
                    int s = c >> 3;
                    int bb = arow >> 8;
                    int ll = (arow & 255) + s - 4;
                    int lc = min(max(ll, 0), 255);
                    src = A + ((long)(bb * 256 + lc) * 512) + (k0 & 511) + q * 8;
                    sz = ((mbits[it] >> s) & 1u) ? 16 : 0;
                } else {
                    src = A + (long)arow * strideA + k0 + q * 8;
                }
                cp16(abase + sw128(r * 128 + q * 16), src, sz);
            }
#pragma unroll
            for (int it = 0; it < BIT; it++) {
                int idx = tid + 256 * it;
                int r = idx >> 3, q = idx & 7;
                int bn = col0 + r;
                int bc = min(bn, N - 1);
                int sz = (bn < N) ? 16 : 0;
                cp16(bbase + sw128(r * 128 + q * 16),
                     W + (long)bc * strideW + k0 + q * 8, sz);
            }
        }
        asm volatile("cp.async.commit_group;" ::: "memory");
    };

#pragma unroll
    for (int s = 0; s < NS - 1; s++) issue(s);

    const int arow_l = (lane & 7) + ((lane >> 3) & 1) * 8;
    const int akh = (lane >> 4) & 1;
    const int brow_l = (lane & 7) + ((lane >> 4) & 1) * 8;
    const int bkh = (lane >> 3) & 1;

    for (int c = 0; c < nchunks; c++) {
        asm volatile("cp.async.wait_group %0;" :: "n"(NS - 2) : "memory");
        __syncthreads();
        issue(c + NS - 1);

        const uint32_t Ab = sb + (c % NS) * STAGEB;
        const uint32_t Bb = Ab + ABYTES;
#pragma unroll
        for (int ks = 0; ks < 4; ks++) {
            uint32_t a[MF][4];
#pragma unroll
            for (int mf = 0; mf < MF; mf++) {
                int row = (wm * MF + mf) * 16 + arow_l;
                ldsm_x4(a[mf][0], a[mf][1], a[mf][2], a[mf][3],
                        Ab + sw128(row * 128 + ks * 32 + akh * 16));
            }
            uint32_t b[NF][2];
#pragma unroll
            for (int ng = 0; ng < NF / 2; ng++) {
                int nrow = (wn * NF + 2 * ng) * 8 + brow_l;
                uint32_t r0, r1, r2, r3;
                ldsm_x4(r0, r1, r2, r3,
                        Bb + sw128(nrow * 128 + ks * 32 + bkh * 16));
                b[2 * ng][0] = r0; b[2 * ng][1] = r1;
                b[2 * ng + 1][0] = r2; b[2 * ng + 1][1] = r3;
            }
#pragma unroll
            for (int mf = 0; mf < MF; mf++)
#pragma unroll
                for (int nf = 0; nf < NF; nf++)
                    mma_f16(acc[mf][nf], a[mf][0], a[mf][1], a[mf][2], a[mf][3],
                            b[nf][0], b[nf][1]);
        }
    }

    // ---- epilogue ----
#pragma unroll
    for (int mf = 0; mf < MF; mf++) {
        int r0 = row0 + (wm * MF + mf) * 16 + grp;
        int r1 = r0 + 8;
#pragma unroll
        for (int nf = 0; nf < NF; nf++) {
            int cb = col0 + (wn * NF + nf) * 8 + tig * 2;
            if (cb >= N) continue;
            float v0 = acc[mf][nf][0], v1 = acc[mf][nf][1];
            float v2 = acc[mf][nf][2], v3 = acc[mf][nf][3];
            if (bias) {
                float b0 = bias[cb], b1 = bias[cb + 1];
                v0 += b0; v1 += b1; v2 += b0; v3 += b1;
            }
            if (epilogue == 1) {
                v0 = (v0 > 0.f) ? v0 : 0.01f * v0;
                v1 = (v1 > 0.f) ? v1 : 0.01f * v1;
                v2 = (v2 > 0.f) ? v2 : 0.01f * v2;
                v3 = (v3 > 0.f) ? v3 : 0.01f * v3;
            }
            if (resid) {
                v0 += resid[(long)r0 * N + cb]; v1 += resid[(long)r0 * N + cb + 1];
                v2 += resid[(long)r1 * N + cb]; v3 += resid[(long)r1 * N + cb + 1];
            }
            if (C) {
                *(float2*)(C + (long)r0 * N + cb) = make_float2(v0, v1);
                *(float2*)(C + (long)r1 * N + cb) = make_float2(v2, v3);
            }
            if (C16) {
                *(__half2*)(C16 + (long)r0 * N + cb) = __floats2half2_rn(v0, v1);
                *(__half2*)(C16 + (long)r1 * N + cb) = __floats2half2_rn(v2, v3);
            }
        }
    }
}

// =====================================================================
// tensor-core attention (round-12 shape: 64 q rows per CTA)
// =====================================================================
#define ATT_SM_Q 0
#define ATT_SM_K 8192
#define ATT_SM_V 40960
#define ATT_SM_P 73728
#define ATT_SM_RED 106496
#define ATT_SMEM (106496 + 2048)

__device__ __forceinline__ uint32_t swp(int r, int c2) {
    return (uint32_t)(r * 512 + (c2 ^ ((r & 7) << 4)));
}

__global__ __launch_bounds__(256) void attn_mma(
    const __half* __restrict__ qkv, const __half* __restrict__ head,
    const __half* __restrict__ headT, const int* __restrict__ mask,
    const float* __restrict__ relw, int layer, __half* __restrict__ ctx)
{
    extern __shared__ char sma[];
    uint32_t sbase = smem_u32(sma);
    const int b = blockIdx.z, hh = blockIdx.y, i0 = blockIdx.x * 64;
    const int tid = threadIdx.x, warp = tid >> 5, lane = tid & 31;
    const int wm = warp >> 2, wn = warp & 3;
    const int r4 = lane >> 2, c2 = (lane & 3) * 2;

    const __half* qb = qkv + (long)b * L_ * 1536 + hh * 64;
    const __half* kb = qb + 512;
    const __half* vb = qb + 1024;

    for (int idx = tid; idx < 64 * 8; idx += 256) {
        int r = idx >> 3, q = idx & 7;
        cp16(sbase + ATT_SM_Q + sw128(r * 128 + q * 16),
             qb + (long)(i0 + r) * 1536 + q * 8, 16);
    }
    for (int idx = tid; idx < 256 * 8; idx += 256) {
        int r = idx >> 3, q = idx & 7;
        cp16(sbase + ATT_SM_K + sw128(r * 128 + q * 16), kb + (long)r * 1536 + q * 8, 16);
        cp16(sbase + ATT_SM_V + sw128(r * 128 + q * 16), vb + (long)r * 1536 + q * 8, 16);
    }
    asm volatile("cp.async.commit_group;" ::: "memory");
    asm volatile("cp.async.wait_group 0;" ::: "memory");
    __syncthreads();

    float acc[2][8][4];
#pragma unroll
    for (int i = 0; i < 2; i++)
#pragma unroll
        for (int j = 0; j < 8; j++)
#pragma unroll
            for (int r = 0; r < 4; r++) acc[i][j][r] = 0.f;

#pragma unroll
    for (int kk = 0; kk < 4; kk++) {
        uint32_t a[2][4];
#pragma unroll
        for (int mf = 0; mf < 2; mf++) {
            int row = wm * 32 + mf * 16 + (lane & 7) + ((lane >> 3) & 1) * 8;
            int kh = (lane >> 4) & 1;
            ldsm_x4(a[mf][0], a[mf][1], a[mf][2], a[mf][3],
                    sbase + ATT_SM_Q + sw128(row * 128 + kk * 32 + kh * 16));
        }
        uint32_t bf[8][2];
#pragma unroll
        for (int ng = 0; ng < 4; ng++) {
            int nrow = wn * 64 + ng * 16 + (lane & 7) + ((lane >> 4) & 1) * 8;
            int kh = (lane >> 3) & 1;
            uint32_t r0, r1, r2, r3;
            ldsm_x4(r0, r1, r2, r3,
                    sbase + ATT_SM_K + sw128(nrow * 128 + kk * 32 + kh * 16));
            bf[2 * ng][0] = r0; bf[2 * ng][1] = r1;
            bf[2 * ng + 1][0] = r2; bf[2 * ng + 1][1] = r3;
        }
#pragma unroll
        for (int mf = 0; mf < 2; mf++)
#pragma unroll
            for (int nf = 0; nf < 8; nf++)
                mma_f16(acc[mf][nf], a[mf][0], a[mf][1], a[mf][2], a[mf][3],
                        bf[nf][0], bf[nf][1]);
    }

    float w0, w1;
    {
        float a0v = relw[(layer * NH_ + hh) * 2 + 0];
        float a1v = relw[(layer * NH_ + hh) * 2 + 1];
        float mv = fmaxf(a0v, a1v);
        float e0 = __expf(a0v - mv), e1 = __expf(a1v - mv);
        w0 = e0 / (e0 + e1); w1 = e1 / (e0 + e1);
    }

#pragma unroll
    for (int nf = 0; nf < 8; nf++) {
        int j = wn * 64 + nf * 8 + c2;
        int m0 = mask[b * L_ + j], m1 = mask[b * L_ + j + 1];
#pragma unroll
        for (int mf = 0; mf < 2; mf++) {
            int ia = i0 + wm * 32 + mf * 16 + r4;
            float2 hd = __half22float2(*(const __half2*)(head + ((long)(b * L_ + ia)) * L_ + j));
            float2 ht = __half22float2(*(const __half2*)(headT + ((long)(b * L_ + ia)) * L_ + j));
            float s0 = acc[mf][nf][0] * 0.125f + w0 * hd.x + w1 * ht.x;
            float s1 = acc[mf][nf][1] * 0.125f + w0 * hd.y + w1 * ht.y;
            acc[mf][nf][0] = m0 ? s0 : -1e30f;
            acc[mf][nf][1] = m1 ? s1 : -1e30f;
            int ib = ia + 8;
            float2 hd2 = __half22float2(*(const __half2*)(head + ((long)(b * L_ + ib)) * L_ + j));
            float2 ht2 = __half22float2(*(const __half2*)(headT + ((long)(b * L_ + ib)) * L_ + j));
            float s2 = acc[mf][nf][2] * 0.125f + w0 * hd2.x + w1 * ht2.x;
            float s3 = acc[mf][nf][3] * 0.125f + w0 * hd2.y + w1 * ht2.y;
            acc[mf][nf][2] = m0 ? s2 : -1e30f;
            acc[mf][nf][3] = m1 ? s3 : -1e30f;
        }
    }

    float* redm = (float*)(sma + ATT_SM_RED);
    float* reds = redm + 256;
    float mx[4];
#pragma unroll
    for (int mf = 0; mf < 2; mf++)
#pragma unroll
        for (int hf = 0; hf < 2; hf++) {
            float m = -1e30f;
#pragma unroll
            for (int nf = 0; nf < 8; nf++)
                m = fmaxf(m, fmaxf(acc[mf][nf][2 * hf], acc[mf][nf][2 * hf + 1]));
            mx[mf * 2 + hf] = m;
        }
#pragma unroll
    for (int ri = 0; ri < 4; ri++) {
        mx[ri] = fmaxf(mx[ri], __shfl_xor_sync(0xffffffffu, mx[ri], 1));
        mx[ri] = fmaxf(mx[ri], __shfl_xor_sync(0xffffffffu, mx[ri], 2));
    }
    if ((lane & 3) == 0) {
#pragma unroll
        for (int mf = 0; mf < 2; mf++)
#pragma unroll
            for (int hf = 0; hf < 2; hf++)
                redm[wn * 64 + wm * 32 + mf * 16 + hf * 8 + r4] = mx[mf * 2 + hf];
    }
    __syncthreads();
    float MX[4];
#pragma unroll
    for (int mf = 0; mf < 2; mf++)
#pragma unroll
        for (int hf = 0; hf < 2; hf++) {
            int row = wm * 32 + mf * 16 + hf * 8 + r4;
            float m = redm[row];
            m = fmaxf(m, redm[64 + row]);
            m = fmaxf(m, redm[128 + row]);
            m = fmaxf(m, redm[192 + row]);
            MX[mf * 2 + hf] = m;
        }
    float sm[4] = {0.f, 0.f, 0.f, 0.f};
#pragma unroll
    for (int mf = 0; mf < 2; mf++)
#pragma unroll
        for (int nf = 0; nf < 8; nf++)
#pragma unroll
            for (int hf = 0; hf < 2; hf++) {
                float e0 = __expf(acc[mf][nf][2 * hf] - MX[mf * 2 + hf]);
                float e1 = __expf(acc[mf][nf][2 * hf + 1] - MX[mf * 2 + hf]);
                acc[mf][nf][2 * hf] = e0;
                acc[mf][nf][2 * hf + 1] = e1;
                sm[mf * 2 + hf] += e0 + e1;
            }
#pragma unroll
    for (int ri = 0; ri < 4; ri++) {
        sm[ri] += __shfl_xor_sync(0xffffffffu, sm[ri], 1);
        sm[ri] += __shfl_xor_sync(0xffffffffu, sm[ri], 2);
    }
    if ((lane & 3) == 0) {
#pragma unroll
        for (int mf = 0; mf < 2; mf++)
#pragma unroll
            for (int hf = 0; hf < 2; hf++)
                reds[wn * 64 + wm * 32 + mf * 16 + hf * 8 + r4] = sm[mf * 2 + hf];
    }
    __syncthreads();
    float inv[4];
#pragma unroll
    for (int mf = 0; mf < 2; mf++)
#pragma unroll
        for (int hf = 0; hf < 2; hf++) {
            int row = wm * 32 + mf * 16 + hf * 8 + r4;
            float t = reds[row] + reds[64 + row] + reds[128 + row] + reds[192 + row];
            inv[mf * 2 + hf] = 1.f / t;
        }

#pragma unroll
    for (int mf = 0; mf < 2; mf++)
#pragma unroll
        for (int nf = 0; nf < 8; nf++) {
            int rowa = wm * 32 + mf * 16 + r4;
            int j = wn * 64 + nf * 8 + c2;
            *(uint32_t*)(sma + ATT_SM_P + swp(rowa, j * 2)) =
                pack_h2(acc[mf][nf][0] * inv[mf * 2], acc[mf][nf][1] * inv[mf * 2]);
            *(uint32_t*)(sma + ATT_SM_P + swp(rowa + 8, j * 2)) =
                pack_h2(acc[mf][nf][2] * inv[mf * 2 + 1], acc[mf][nf][3] * inv[mf * 2 + 1]);
        }
    __syncthreads();

    float oacc[2][2][4];
#pragma unroll
    for (int i = 0; i < 2; i++)
#pragma unroll
        for (int j = 0; j < 2; j++)
#pragma unroll
            for (int r = 0; r < 4; r++) oacc[i][j][r] = 0.f;

#pragma unroll
    for (int kk = 0; kk < 16; kk++) {
        uint32_t a[2][4];
#pragma unroll
        for (int mf = 0; mf < 2; mf++) {
            int row = wm * 32 + mf * 16 + (lane & 7) + ((lane >> 3) & 1) * 8;
            int kh = (lane >> 4) & 1;
            ldsm_x4(a[mf][0], a[mf][1], a[mf][2], a[mf][3],
                    sbase + ATT_SM_P + swp(row, kk * 32 + kh * 16));
        }
        uint32_t bf[2][2];
        {
            int kvrow = kk * 16 + (lane & 7) + ((lane >> 3) & 1) * 8;
            int nb = wn * 16 + ((lane >> 4) & 1) * 8;
            uint32_t r0, r1, r2, r3;
            ldsm_x4_t(r0, r1, r2, r3,
                      sbase + ATT_SM_V + sw128(kvrow * 128 + nb * 2));
            bf[0][0] = r0; bf[0][1] = r1; bf[1][0] = r2; bf[1][1] = r3;
        }
#pragma unroll
        for (int mf = 0; mf < 2; mf++)
#pragma unroll
            for (int nf = 0; nf < 2; nf++)
                mma_f16(oacc[mf][nf], a[mf][0], a[mf][1], a[mf][2], a[mf][3],
                        bf[nf][0], bf[nf][1]);
    }

#pragma unroll
    for (int mf = 0; mf < 2; mf++)
#pragma unroll
        for (int nf = 0; nf < 2; nf++) {
            int row = i0 + wm * 32 + mf * 16 + r4;
            int d = wn * 16 + nf * 8 + c2;
            __half* dst = ctx + ((long)(b * L_) + row) * H_ + hh * 64 + d;
            *(__half2*)dst = __floats2half2_rn(oacc[mf][nf][0], oacc[mf][nf][1]);
            *(__half2*)(dst + 8 * H_) = __floats2half2_rn(oacc[mf][nf][2], oacc[mf][nf][3]);
        }
}

// ---------------- embed + mask ----------------
__global__ void embed_kernel(const int* __restrict__ x, const float* __restrict__ emb,
                             float* __restrict__ h, __half* __restrict__ h16,
                             int* __restrict__ mask) {
    int r = blockIdx.x;
    int tok = x[r];
    if (threadIdx.x == 0) mask[r] = (tok != 0) ? 1 : 0;
    const float* e = emb + (long)tok * H_;
    float v0 = e[threadIdx.x];
    float v1 = e[threadIdx.x + 256];
    float* o = h + (long)r * H_;
    o[threadIdx.x] = v0;
    o[threadIdx.x + 256] = v1;
    __half* o16 = h16 + (long)r * H_;
    o16[threadIdx.x] = __float2half(v0);
    o16[threadIdx.x + 256] = __float2half(v1);
}

// ---------------- warp-per-row layernorm: no smem, no barriers ----------------
// 256 threads = 8 warps = 8 rows per block. Lane l holds cols {i*128 + l*4 .. +3}.
__global__ __launch_bounds__(256) void ln_kernel(
    const float* __restrict__ in, const __half* __restrict__ in16,
    float* __restrict__ out, __half* __restrict__ out16,
    const float* __restrict__ s, const float* __restrict__ b,
    int do_tanh) {
    const int warp = threadIdx.x >> 5, lane = threadIdx.x & 31;
    const long r = (long)blockIdx.x * 8 + warp;
    float v[16];
    if (in16) {
        const __half* x = in16 + r * H_;
#pragma unroll
        for (int i = 0; i < 4; i++) {
            uint2 u = *(const uint2*)(x + i * 128 + lane * 4);
            float2 f0 = __half22float2(*reinterpret_cast<__half2*>(&u.x));
            float2 f1 = __half22float2(*reinterpret_cast<__half2*>(&u.y));
            v[i * 4 + 0] = f0.x; v[i * 4 + 1] = f0.y;
            v[i * 4 + 2] = f1.x; v[i * 4 + 3] = f1.y;
        }
    } else {
        const float* x = in + r * H_;
#pragma unroll
        for (int i = 0; i < 4; i++) {
            float4 f = *(const float4*)(x + i * 128 + lane * 4);
            v[i * 4 + 0] = f.x; v[i * 4 + 1] = f.y;
            v[i * 4 + 2] = f.z; v[i * 4 + 3] = f.w;
        }
    }
    float sa = 0.f, sq = 0.f;
#pragma unroll
    for (int i = 0; i < 16; i++) { sa += v[i]; sq += v[i] * v[i]; }
#pragma unroll
    for (int o = 16; o; o >>= 1) {
        sa += __shfl_xor_sync(0xffffffffu, sa, o);
        sq += __shfl_xor_sync(0xffffffffu, sq, o);
    }
    float m = sa * (1.f / 512.f);
    float var = sq * (1.f / 512.f) - m * m;
    float inv = rsqrtf(var + 1e-5f);
#pragma unroll
    for (int i = 0; i < 4; i++) {
        float y[4];
#pragma unroll
        for (int q = 0; q < 4; q++) y[q] = (v[i * 4 + q] - m) * inv;
        if (s) {
            float4 sv = *(const float4*)(s + i * 128 + lane * 4);
            float4 bv = *(const float4*)(b + i * 128 + lane * 4);
            y[0] = y[0] * sv.x + bv.x; y[1] = y[1] * sv.y + bv.y;
            y[2] = y[2] * sv.z + bv.z; y[3] = y[3] * sv.w + bv.w;
        }
        if (do_tanh) {
#pragma unroll
            for (int q = 0; q < 4; q++) y[q] = tanhf(y[q]);
        }
        if (out)
            *(float4*)(out + r * H_ + i * 128 + lane * 4) =
                make_float4(y[0], y[1], y[2], y[3]);
        if (out16)
            *(uint2*)(out16 + r * H_ + i * 128 + lane * 4) =
                make_uint2(pack_h2(y[0], y[1]), pack_h2(y[2], y[3]));
    }
}

// ---------------- parse softmax (fp16 in-place) ----------------
__device__ __forceinline__ float block_sum_8w(float v, float* red) {
    int lane = threadIdx.x & 31, w = threadIdx.x >> 5;
#pragma unroll
    for (int o = 16; o; o >>= 1) v += __shfl_xor_sync(0xffffffffu, v, o);
    if (lane == 0) red[w] = v;
    __syncthreads();
    float t = (lane < 8) ? red[lane] : 0.f;
#pragma unroll
    for (int o = 4; o; o >>= 1) t += __shfl_xor_sync(0xffffffffu, t, o);
    return __shfl_sync(0xffffffffu, t, 0);
}

__global__ void softmax_head_kernel(__half* __restrict__ head16,
                                    const int* __restrict__ mask) {
    __shared__ float red[32];
    int bi = blockIdx.x;
    int b = bi >> 8, i = bi & 255;
    __half* row = head16 + (long)bi * L_;
    int j = threadIdx.x;
    float v = (mask[b * L_ + j] != 0) ? __half2float(row[j]) * (1.f / 512.f) : -INFINITY;

    int lane = threadIdx.x & 31, w = threadIdx.x >> 5;
    float m = v;
#pragma unroll
    for (int o = 16; o; o >>= 1) m = fmaxf(m, __shfl_xor_sync(0xffffffffu, m, o));
    if (lane == 0) red[w] = m;
    __syncthreads();
    float t = (lane < 8) ? red[lane] : -INFINITY;
#pragma unroll
    for (int o = 4; o; o >>= 1) t = fmaxf(t, __shfl_xor_sync(0xffffffffu, t, o));
    m = __shfl_sync(0xffffffffu, t, 0);
    __syncthreads();

    float e = (v == -INFINITY) ? 0.f : __expf(v - m);
    float sum = block_sum_8w(e, red);
    float p = (sum > 0.f) ? e / sum : 0.f;
    if (j == i) p = 0.f;
    row[j] = __float2half(p);
}

// ---------------- head transpose (fp16) ----------------
__global__ void transpose16_kernel(const __half* __restrict__ head,
                                   __half* __restrict__ headT) {
    __shared__ __half t[32][34];
    int b = blockIdx.z;
    int i0 = blockIdx.y * 32, j0 = blockIdx.x * 32;
    const __half* src = head + (long)b * L_ * L_;
    t[threadIdx.y][threadIdx.x] = src[(long)(i0 + threadIdx.y) * L_ + j0 + threadIdx.x];
    __syncthreads();
    headT[(long)b * L_ * L_ + (long)(j0 + threadIdx.y) * L_ + i0 + threadIdx.x] =
        t[threadIdx.x][threadIdx.y];
}

// ---------------- host orchestration ----------------
#define GSM_SMALL (4 * (128 * 128 + 64 * 128))      // 98304 (4 stages)
#define GSM_BIG   (3 * (128 * 128 + 128 * 128))     // 98304 (3 stages)

static inline void launch_h(const __half* A, const __half* W, const float* bias,
                            const float* resid, float* C, __half* C16, const int* mask,
                            int M, int N, int Kd, int epilogue,
                            int conv_mode = 0, int strideA = -1, int strideW = -1,
                            int batch = 1, long sA = 0, long sB = 0, long sC = 0) {
    if (strideA < 0) strideA = Kd;
    if (strideW < 0) strideW = Kd;
    if (N <= 512) {
        dim3 g((N + 63) / 64, M / 128, batch);
        gemm_h<4, 2, 2, 4, 4><<<g, 256, GSM_SMALL>>>(A, W, bias, resid, C, C16, mask,
                                                     M, N, Kd, strideA, strideW,
                                                     sA, sB, sC, epilogue, conv_mode);
    } else {
        dim3 g((N + 127) / 128, M / 128, batch);
        gemm_h<2, 4, 4, 4, 3><<<g, 256, GSM_BIG>>>(A, W, bias, resid, C, C16, mask,
                                                   M, N, Kd, strideA, strideW,
                                                   sA, sB, sC, epilogue, conv_mode);
    }
}

extern "C" void kernel_launch(void* const* d_in, const int* in_sizes, int n_in,
                              void* d_out, int out_size) {
    const int*   x        = (const int*)d_in[0];
    const float* emb      = (const float*)d_in[2];
    const float* conv_w   = (const float*)d_in[3];
    const float* conv_b   = (const float*)d_in[4];
    const float* parent_w = (const float*)d_in[5];
    const float* parent_b = (const float*)d_in[6];
    const float* child_w  = (const float*)d_in[7];
    const float* child_b  = (const float*)d_in[8];
    const float* rel_w    = (const float*)d_in[9];
    const float* qkv_w    = (const float*)d_in[10];
    const float* qkv_b    = (const float*)d_in[11];
    const float* out_w    = (const float*)d_in[12];
    const float* out_b    = (const float*)d_in[13];
    const float* ln1_s    = (const float*)d_in[14];
    const float* ln1_b    = (const float*)d_in[15];
    const float* ln2_s    = (const float*)d_in[16];
    const float* ln2_b    = (const float*)d_in[17];
    const float* ff1_w    = (const float*)d_in[18];
    const float* ff1_b    = (const float*)d_in[19];
    const float* ff2_w    = (const float*)d_in[20];
    const float* ff2_b    = (const float*)d_in[21];
    const float* norm_s   = (const float*)d_in[22];
    const float* norm_b   = (const float*)d_in[23];
    const float* out_bias = (const float*)d_in[24];
    float* out = (float*)d_out;

    void *p;
    cudaGetSymbolAddress(&p, g_h);        float*  h       = (float*)p;
    cudaGetSymbolAddress(&p, g_pcb);      float*  pcb     = (float*)p;
    cudaGetSymbolAddress(&p, g_mask);     int*    mask    = (int*)p;
    cudaGetSymbolAddress(&p, g_head16);   __half* head16  = (__half*)p;
    cudaGetSymbolAddress(&p, g_headT16);  __half* headT16 = (__half*)p;
    cudaGetSymbolAddress(&p, g_h16);      __half* h16     = (__half*)p;
    cudaGetSymbolAddress(&p, g_hn16);     __half* hn16    = (__half*)p;
    cudaGetSymbolAddress(&p, g_pc16);     __half* pc16    = (__half*)p;
    cudaGetSymbolAddress(&p, g_qkv16);    __half* qkv16   = (__half*)p;
    cudaGetSymbolAddress(&p, g_ctx16);    __half* ctx16   = (__half*)p;
    cudaGetSymbolAddress(&p, g_ff16);     __half* ff16    = (__half*)p;
    cudaGetSymbolAddress(&p, g_convT16);  __half* convT16 = (__half*)p;
    cudaGetSymbolAddress(&p, g_qkvw16);   __half* qkvw16  = (__half*)p;
    cudaGetSymbolAddress(&p, g_outw16);   __half* outw16  = (__half*)p;
    cudaGetSymbolAddress(&p, g_ff1w16);   __half* ff1w16  = (__half*)p;
    cudaGetSymbolAddress(&p, g_ff2w16);   __half* ff2w16  = (__half*)p;
    cudaGetSymbolAddress(&p, g_pcw16);    __half* pcw16   = (__half*)p;
    cudaGetSymbolAddress(&p, g_emb16);    __half* emb16   = (__half*)p;

    cudaFuncSetAttribute(attn_mma, cudaFuncAttributeMaxDynamicSharedMemorySize, ATT_SMEM);
    cudaFuncSetAttribute(gemm_h<4, 2, 2, 4, 4>,
                         cudaFuncAttributeMaxDynamicSharedMemorySize, GSM_SMALL);
    cudaFuncSetAttribute(gemm_h<2, 4, 4, 4, 3>,
                         cudaFuncAttributeMaxDynamicSharedMemorySize, GSM_BIG);

    // ---- weight conversions ----
    convw_transpose16<<<dim3(16, 16, P_ * KW_), dim3(32, 32)>>>(conv_w, convT16);
    {
        CvtJobs j;
        j.src[0] = qkv_w;    j.dst[0] = qkvw16;           j.n4[0] = NL_ * 3 * H_ * H_ / 4;
        j.src[1] = out_w;    j.dst[1] = outw16;           j.n4[1] = NL_ * H_ * H_ / 4;
        j.src[2] = ff1_w;    j.dst[2] = ff1w16;           j.n4[2] = NL_ * DFF_ * H_ / 4;
        j.src[3] = ff2_w;    j.dst[3] = ff2w16;           j.n4[3] = NL_ * H_ * DFF_ / 4;
        j.src[4] = parent_w; j.dst[4] = pcw16;            j.n4[4] = H_ * H_ / 4;
        j.src[5] = child_w;  j.dst[5] = pcw16 + 512 * H_; j.n4[5] = H_ * H_ / 4;
        j.src[6] = emb;      j.dst[6] = emb16;            j.n4[6] = NTOK_ * H_ / 4;
        int total4 = 0;
        for (int k = 0; k < 7; k++) total4 += j.n4[k];
        cvt_multi<<<(total4 + 255) / 256, 256>>>(j, total4);
    }
    concat_bias<<<4, 256>>>(parent_b, child_b, pcb);

    // ---- embedding + mask ----
    embed_kernel<<<BL_, 256>>>(x, emb, h, h16, mask);

    // ---- parser ----
    for (int pl = 0; pl < P_; pl++) {
        launch_h(h16, convT16 + (long)pl * H_ * KW_ * H_, conv_b + pl * H_,
                 nullptr, nullptr, hn16, mask, BL_, H_, KW_ * H_, 0,
                 /*conv_mode=*/1, /*strideA=*/H_);
        ln_kernel<<<BL_ / 8, 256>>>(nullptr, hn16, nullptr, h16, nullptr, nullptr, 1);
    }

    // ---- parent+child combined GEMM ----
    launch_h(h16, pcw16, pcb, nullptr, nullptr, pc16, mask, BL_, 1024, H_, 0);

    // ---- parse logits + softmax + transpose ----
    launch_h(pc16 + 512, pc16, nullptr, nullptr, nullptr, head16, mask,
             L_, L_, H_, 0, 0, /*strideA=*/1024, /*strideW=*/1024,
             B_, (long)L_ * 1024, (long)L_ * 1024, (long)L_ * L_);
    softmax_head_kernel<<<BL_, 256>>>(head16, mask);
    transpose16_kernel<<<dim3(8, 8, B_), dim3(32, 32)>>>(head16, headT16);

    // ---- transformer ----
    for (int i = 0; i < NL_; i++) {
        ln_kernel<<<BL_ / 8, 256>>>(h, nullptr, nullptr, hn16,
                                    ln1_s + i * H_, ln1_b + i * H_, 0);
        launch_h(hn16, qkvw16 + (long)i * 3 * H_ * H_, qkv_b + i * 3 * H_,
                 nullptr, nullptr, qkv16, mask, BL_, 3 * H_, H_, 0);
        attn_mma<<<dim3(4, NH_, B_), 256, ATT_SMEM>>>(qkv16, head16, headT16, mask,
                                                      rel_w, i, ctx16);
        launch_h(ctx16, outw16 + (long)i * H_ * H_, out_b + i * H_, h, h, nullptr, mask,
                 BL_, H_, H_, 0);
        ln_kernel<<<BL_ / 8, 256>>>(h, nullptr, nullptr, hn16,
                                    ln2_s + i * H_, ln2_b + i * H_, 0);
        launch_h(hn16, ff1w16 + (long)i * DFF_ * H_, ff1_b + i * DFF_,
                 nullptr, nullptr, ff16, mask, BL_, DFF_, H_, 1);
        launch_h(ff16, ff2w16 + (long)i * H_ * DFF_, ff2_b + i * H_, h, h, nullptr, mask,
                 BL_, H_, DFF_, 0);
    }

    // ---- final LN + tied output ----
    ln_kernel<<<BL_ / 8, 256>>>(h, nullptr, nullptr, hn16, norm_s, norm_b, 0);
    launch_h(hn16, emb16, out_bias, nullptr, out, nullptr, mask, BL_, NTOK_, H_, 0);
}

// round 16
// speedup vs baseline: 1.0485x; 1.0029x over previous
#include <cuda_runtime.h>
#include <cuda_fp16.h>
#include <math.h>
#include <stdint.h>

#define B_ 16
#define L_ 256
#define H_ 512
#define NH_ 8
#define DH_ 64
#define NL_ 6
#define NTOK_ 10000
#define P_ 4
#define KW_ 9
#define DFF_ 2048
#define BL_ (B_ * L_)

// ---------------- device scratch (fp32) ----------------
__device__ float g_h[BL_ * H_];
__device__ float g_pcb[1024];
__device__ int   g_mask[BL_];
// ---------------- device scratch (fp16) ----------------
__device__ __half g_head16[B_ * L_ * L_];
__device__ __half g_headT16[B_ * L_ * L_];
__device__ __half g_h16[BL_ * H_];
__device__ __half g_hn16[BL_ * H_];
__device__ __half g_pc16[BL_ * 1024];
__device__ __half g_qkv16[BL_ * 3 * H_];
__device__ __half g_ctx16[BL_ * H_];
__device__ __half g_ff16[BL_ * DFF_];
// fp16 weights
__device__ __half g_convT16[P_ * H_ * KW_ * H_];
__device__ __half g_qkvw16[NL_ * 3 * H_ * H_];
__device__ __half g_outw16[NL_ * H_ * H_];
__device__ __half g_ff1w16[NL_ * DFF_ * H_];
__device__ __half g_ff2w16[NL_ * H_ * DFF_];
__device__ __half g_pcw16[1024 * H_];
__device__ __half g_emb16[NTOK_ * H_];

// ================= helpers =================
__device__ __forceinline__ uint32_t pack_h2(float x, float y) {
    __half2 h = __floats2half2_rn(x, y);
    return *reinterpret_cast<uint32_t*>(&h);
}
__device__ __forceinline__ uint32_t smem_u32(const void* p) {
    uint32_t a;
    asm("{ .reg .u64 t; cvta.to.shared.u64 t, %1; cvt.u32.u64 %0, t; }" : "=r"(a) : "l"(p));
    return a;
}
__device__ __forceinline__ uint32_t sw128(uint32_t x) { return x ^ ((x >> 3) & 0x70); }

__device__ __forceinline__ void mma_f16(float c[4], uint32_t a0, uint32_t a1,
                                        uint32_t a2, uint32_t a3,
                                        uint32_t b0, uint32_t b1) {
    asm volatile(
        "mma.sync.aligned.m16n8k16.row.col.f32.f16.f16.f32 "
        "{%0,%1,%2,%3}, {%4,%5,%6,%7}, {%8,%9}, {%0,%1,%2,%3};\n"
        : "+f"(c[0]), "+f"(c[1]), "+f"(c[2]), "+f"(c[3])
        : "r"(a0), "r"(a1), "r"(a2), "r"(a3), "r"(b0), "r"(b1));
}
__device__ __forceinline__ void ldsm_x4(uint32_t& r0, uint32_t& r1, uint32_t& r2,
                                        uint32_t& r3, uint32_t addr) {
    asm volatile("ldmatrix.sync.aligned.m8n8.x4.shared.b16 {%0,%1,%2,%3}, [%4];"
                 : "=r"(r0), "=r"(r1), "=r"(r2), "=r"(r3) : "r"(addr));
}
__device__ __forceinline__ void ldsm_x4_t(uint32_t& r0, uint32_t& r1, uint32_t& r2,
                                          uint32_t& r3, uint32_t addr) {
    asm volatile("ldmatrix.sync.aligned.m8n8.x4.trans.shared.b16 {%0,%1,%2,%3}, [%4];"
                 : "=r"(r0), "=r"(r1), "=r"(r2), "=r"(r3) : "r"(addr));
}
__device__ __forceinline__ void cp16(uint32_t dst, const __half* src, int sz) {
    asm volatile("cp.async.cg.shared.global [%0], [%1], 16, %2;"
                 :: "r"(dst), "l"(__cvta_generic_to_global(src)), "r"(sz));
}

// ---------------- fused fp32 -> fp16 conversion ----------------
struct CvtJobs {
    const float* src[7];
    __half* dst[7];
    int n4[7];
};
__global__ void cvt_multi(CvtJobs j, int total4) {
    int i = blockIdx.x * 256 + threadIdx.x;
    if (i >= total4) return;
    int s = 0, base = 0;
    while (i - base >= j.n4[s]) { base += j.n4[s]; s++; }
    int o = i - base;
    float4 v = *(const float4*)(j.src[s] + (long)o * 4);
    *(uint2*)(j.dst[s] + (long)o * 4) = make_uint2(pack_h2(v.x, v.y), pack_h2(v.z, v.w));
}

// conv weights: w[p][k][ci][co] -> wt16[p][co][k*H+ci]
__global__ void convw_transpose16(const float* __restrict__ w, __half* __restrict__ wt) {
    __shared__ float t[32][33];
    int pk = blockIdx.z;
    int p = pk / KW_, k = pk % KW_;
    int ci0 = blockIdx.y * 32, co0 = blockIdx.x * 32;
    t[threadIdx.y][threadIdx.x] =
        w[((long)pk * H_ + ci0 + threadIdx.y) * H_ + co0 + threadIdx.x];
    __syncthreads();
    wt[((long)p * H_ + co0 + threadIdx.y) * (KW_ * H_) + k * H_ + ci0 + threadIdx.x] =
        __float2half(t[threadIdx.x][threadIdx.y]);
}

__global__ void concat_bias(const float* __restrict__ a, const float* __restrict__ b,
                            float* __restrict__ o) {
    int i = blockIdx.x * 256 + threadIdx.x;
    if (i < 512) o[i] = a[i];
    else if (i < 1024) o[i] = b[i - 512];
}

// =====================================================================
// fp16 GEMM: 256 threads, cp.async NS-stage, SW128 + ldmatrix, 2 CTAs/SM.
// =====================================================================
template <int WM, int WN, int MF, int NF, int NS>
__global__ __launch_bounds__(256, 2) void gemm_h(
    const __half* __restrict__ A, const __half* __restrict__ W,
    const float* __restrict__ bias, const float* __restrict__ resid,
    float* __restrict__ C, __half* __restrict__ C16,
    const int* __restrict__ cmask,
    int M, int N, int Kd, int strideA, int strideW,
    long sA, long sB, long sC,
    int epilogue, int conv_mode)
{
    constexpr int BM = WM * MF * 16;
    constexpr int BN = WN * NF * 8;
    constexpr int ABYTES = BM * 128;
    constexpr int BBYTES = BN * 128;
    constexpr int STAGEB = ABYTES + BBYTES;
    constexpr int AIT = BM * 8 / 256;
    constexpr int BIT = BN * 8 / 256;

    extern __shared__ char smem[];
    uint32_t sb = smem_u32(smem);

    int bz = blockIdx.z;
    A += (long)bz * sA;
    W += (long)bz * sB;
    if (C) C += (long)bz * sC;
    if (C16) C16 += (long)bz * sC;
    if (resid) resid += (long)bz * sC;

    const int tid = threadIdx.x;
    const int warp = tid >> 5, lane = tid & 31;
    const int wm = warp / WN;
    const int wn = warp % WN;
    const int grp = lane >> 2, tig = lane & 3;
    const int row0 = blockIdx.y * BM;
    const int col0 = blockIdx.x * BN;

    uint32_t mbits[AIT];
    if (conv_mode) {
#pragma unroll
        for (int it = 0; it < AIT; it++) {
            int r = (tid + 256 * it) >> 3;
            int arow = row0 + r;
            int bb = arow >> 8, base = arow & 255;
            uint32_t bits = 0;
#pragma unroll
            for (int s = 0; s < 9; s++) {
                int ll = base + s - 4;
                if (ll >= 0 && ll < 256 && cmask[bb * 256 + ll] != 0)
                    bits |= 1u << s;
            }
            mbits[it] = bits;
        }
    }

    float acc[MF][NF][4];
#pragma unroll
    for (int i = 0; i < MF; i++)
#pragma unroll
        for (int j = 0; j < NF; j++)
#pragma unroll
            for (int r = 0; r < 4; r++) acc[i][j][r] = 0.f;

    const int nchunks = Kd >> 6;

    auto issue = [&](int c) {
        if (c < nchunks) {
            uint32_t abase = sb + (c % NS) * STAGEB;
            uint32_t bbase = abase + ABYTES;
            const int k0 = c << 6;
#pragma unroll
            for (int it = 0; it < AIT; it++) {
                int idx = tid + 256 * it;
                int r = idx >> 3, q = idx & 7;
                int arow = row0 + r;
                const __half* src;
                int sz = 16;
                if (conv_mode) {
                    int s = c >> 3;
                    int bb = arow >> 8;
                    int ll = (arow & 255) + s - 4;
                    int lc = min(max(ll, 0), 255);
                    src = A + ((long)(bb * 256 + lc) * 512) + (k0 & 511) + q * 8;
                    sz = ((mbits[it] >> s) & 1u) ? 16 : 0;
                } else {
                    src = A + (long)arow * strideA + k0 + q * 8;
                }
                cp16(abase + sw128(r * 128 + q * 16), src, sz);
            }
#pragma unroll
            for (int it = 0; it < BIT; it++) {
                int idx = tid + 256 * it;
                int r = idx >> 3, q = idx & 7;
                int bn = col0 + r;
                int bc = min(bn, N - 1);
                int sz = (bn < N) ? 16 : 0;
                cp16(bbase + sw128(r * 128 + q * 16),
                     W + (long)bc * strideW + k0 + q * 8, sz);
            }
        }
        asm volatile("cp.async.commit_group;" ::: "memory");
    };

#pragma unroll
    for (int s = 0; s < NS - 1; s++) issue(s);

    const int arow_l = (lane & 7) + ((lane >> 3) & 1) * 8;
    const int akh = (lane >> 4) & 1;
    const int brow_l = (lane & 7) + ((lane >> 4) & 1) * 8;
    const int bkh = (lane >> 3) & 1;

    for (int c = 0; c < nchunks; c++) {
        asm volatile("cp.async.wait_group %0;" :: "n"(NS - 2) : "memory");
        __syncthreads();
        issue(c + NS - 1);

        const uint32_t Ab = sb + (c % NS) * STAGEB;
        const uint32_t Bb = Ab + ABYTES;
#pragma unroll
        for (int ks = 0; ks < 4; ks++) {
            uint32_t a[MF][4];
#pragma unroll
            for (int mf = 0; mf < MF; mf++) {
                int row = (wm * MF + mf) * 16 + arow_l;
                ldsm_x4(a[mf][0], a[mf][1], a[mf][2], a[mf][3],
                        Ab + sw128(row * 128 + ks * 32 + akh * 16));
            }
            uint32_t b[NF][2];
#pragma unroll
            for (int ng = 0; ng < NF / 2; ng++) {
                int nrow = (wn * NF + 2 * ng) * 8 + brow_l;
                uint32_t r0, r1, r2, r3;
                ldsm_x4(r0, r1, r2, r3,
                        Bb + sw128(nrow * 128 + ks * 32 + bkh * 16));
                b[2 * ng][0] = r0; b[2 * ng][1] = r1;
                b[2 * ng + 1][0] = r2; b[2 * ng + 1][1] = r3;
            }
#pragma unroll
            for (int mf = 0; mf < MF; mf++)
#pragma unroll
                for (int nf = 0; nf < NF; nf++)
                    mma_f16(acc[mf][nf], a[mf][0], a[mf][1], a[mf][2], a[mf][3],
                            b[nf][0], b[nf][1]);
        }
    }

    // ---- epilogue ----
#pragma unroll
    for (int mf = 0; mf < MF; mf++) {
        int r0 = row0 + (wm * MF + mf) * 16 + grp;
        int r1 = r0 + 8;
#pragma unroll
        for (int nf = 0; nf < NF; nf++) {
            int cb = col0 + (wn * NF + nf) * 8 + tig * 2;
            if (cb >= N) continue;
            float v0 = acc[mf][nf][0], v1 = acc[mf][nf][1];
            float v2 = acc[mf][nf][2], v3 = acc[mf][nf][3];
            if (bias) {
                float b0 = bias[cb], b1 = bias[cb + 1];
                v0 += b0; v1 += b1; v2 += b0; v3 += b1;
            }
            if (epilogue == 1) {
                v0 = (v0 > 0.f) ? v0 : 0.01f * v0;
                v1 = (v1 > 0.f) ? v1 : 0.01f * v1;
                v2 = (v2 > 0.f) ? v2 : 0.01f * v2;
                v3 = (v3 > 0.f) ? v3 : 0.01f * v3;
            }
            if (resid) {
                v0 += resid[(long)r0 * N + cb]; v1 += resid[(long)r0 * N + cb + 1];
                v2 += resid[(long)r1 * N + cb]; v3 += resid[(long)r1 * N + cb + 1];
            }
            if (C) {
                *(float2*)(C + (long)r0 * N + cb) = make_float2(v0, v1);
                *(float2*)(C + (long)r1 * N + cb) = make_float2(v2, v3);
            }
            if (C16) {
                *(__half2*)(C16 + (long)r0 * N + cb) = __floats2half2_rn(v0, v1);
                *(__half2*)(C16 + (long)r1 * N + cb) = __floats2half2_rn(v2, v3);
            }
        }
    }
}

// =====================================================================
// tensor-core attention (64 q rows per CTA)
// =====================================================================
#define ATT_SM_Q 0
#define ATT_SM_K 8192
#define ATT_SM_V 40960
#define ATT_SM_P 73728
#define ATT_SM_RED 106496
#define ATT_SMEM (106496 + 2048)

__device__ __forceinline__ uint32_t swp(int r, int c2) {
    return (uint32_t)(r * 512 + (c2 ^ ((r & 7) << 4)));
}

__global__ __launch_bounds__(256) void attn_mma(
    const __half* __restrict__ qkv, const __half* __restrict__ head,
    const __half* __restrict__ headT, const int* __restrict__ mask,
    const float* __restrict__ relw, int layer, __half* __restrict__ ctx)
{
    extern __shared__ char sma[];
    uint32_t sbase = smem_u32(sma);
    const int b = blockIdx.z, hh = blockIdx.y, i0 = blockIdx.x * 64;
    const int tid = threadIdx.x, warp = tid >> 5, lane = tid & 31;
    const int wm = warp >> 2, wn = warp & 3;
    const int r4 = lane >> 2, c2 = (lane & 3) * 2;

    const __half* qb = qkv + (long)b * L_ * 1536 + hh * 64;
    const __half* kb = qb + 512;
    const __half* vb = qb + 1024;

    for (int idx = tid; idx < 64 * 8; idx += 256) {
        int r = idx >> 3, q = idx & 7;
        cp16(sbase + ATT_SM_Q + sw128(r * 128 + q * 16),
             qb + (long)(i0 + r) * 1536 + q * 8, 16);
    }
    for (int idx = tid; idx < 256 * 8; idx += 256) {
        int r = idx >> 3, q = idx & 7;
        cp16(sbase + ATT_SM_K + sw128(r * 128 + q * 16), kb + (long)r * 1536 + q * 8, 16);
        cp16(sbase + ATT_SM_V + sw128(r * 128 + q * 16), vb + (long)r * 1536 + q * 8, 16);
    }
    asm volatile("cp.async.commit_group;" ::: "memory");
    asm volatile("cp.async.wait_group 0;" ::: "memory");
    __syncthreads();

    float acc[2][8][4];
#pragma unroll
    for (int i = 0; i < 2; i++)
#pragma unroll
        for (int j = 0; j < 8; j++)
#pragma unroll
            for (int r = 0; r < 4; r++) acc[i][j][r] = 0.f;

#pragma unroll
    for (int kk = 0; kk < 4; kk++) {
        uint32_t a[2][4];
#pragma unroll
        for (int mf = 0; mf < 2; mf++) {
            int row = wm * 32 + mf * 16 + (lane & 7) + ((lane >> 3) & 1) * 8;
            int kh = (lane >> 4) & 1;
            ldsm_x4(a[mf][0], a[mf][1], a[mf][2], a[mf][3],
                    sbase + ATT_SM_Q + sw128(row * 128 + kk * 32 + kh * 16));
        }
        uint32_t bf[8][2];
#pragma unroll
        for (int ng = 0; ng < 4; ng++) {
            int nrow = wn * 64 + ng * 16 + (lane & 7) + ((lane >> 4) & 1) * 8;
            int kh = (lane >> 3) & 1;
            uint32_t r0, r1, r2, r3;
            ldsm_x4(r0, r1, r2, r3,
                    sbase + ATT_SM_K + sw128(nrow * 128 + kk * 32 + kh * 16));
            bf[2 * ng][0] = r0; bf[2 * ng][1] = r1;
            bf[2 * ng + 1][0] = r2; bf[2 * ng + 1][1] = r3;
        }
#pragma unroll
        for (int mf = 0; mf < 2; mf++)
#pragma unroll
            for (int nf = 0; nf < 8; nf++)
                mma_f16(acc[mf][nf], a[mf][0], a[mf][1], a[mf][2], a[mf][3],
                        bf[nf][0], bf[nf][1]);
    }

    float w0, w1;
    {
        float a0v = relw[(layer * NH_ + hh) * 2 + 0];
        float a1v = relw[(layer * NH_ + hh) * 2 + 1];
        float mv = fmaxf(a0v, a1v);
        float e0 = __expf(a0v - mv), e1 = __expf(a1v - mv);
        w0 = e0 / (e0 + e1); w1 = e1 / (e0 + e1);
    }

#pragma unroll
    for (int nf = 0; nf < 8; nf++) {
        int j = wn * 64 + nf * 8 + c2;
        int m0 = mask[b * L_ + j], m1 = mask[b * L_ + j + 1];
#pragma unroll
        for (int mf = 0; mf < 2; mf++) {
            int ia = i0 + wm * 32 + mf * 16 + r4;
            float2 hd = __half22float2(*(const __half2*)(head + ((long)(b * L_ + ia)) * L_ + j));
            float2 ht = __half22float2(*(const __half2*)(headT + ((long)(b * L_ + ia)) * L_ + j));
            float s0 = acc[mf][nf][0] * 0.125f + w0 * hd.x + w1 * ht.x;
            float s1 = acc[mf][nf][1] * 0.125f + w0 * hd.y + w1 * ht.y;
            acc[mf][nf][0] = m0 ? s0 : -1e30f;
            acc[mf][nf][1] = m1 ? s1 : -1e30f;
            int ib = ia + 8;
            float2 hd2 = __half22float2(*(const __half2*)(head + ((long)(b * L_ + ib)) * L_ + j));
            float2 ht2 = __half22float2(*(const __half2*)(headT + ((long)(b * L_ + ib)) * L_ + j));
            float s2 = acc[mf][nf][2] * 0.125f + w0 * hd2.x + w1 * ht2.x;
            float s3 = acc[mf][nf][3] * 0.125f + w0 * hd2.y + w1 * ht2.y;
            acc[mf][nf][2] = m0 ? s2 : -1e30f;
            acc[mf][nf][3] = m1 ? s3 : -1e30f;
        }
    }

    float* redm = (float*)(sma + ATT_SM_RED);
    float* reds = redm + 256;
    float mx[4];
#pragma unroll
    for (int mf = 0; mf < 2; mf++)
#pragma unroll
        for (int hf = 0; hf < 2; hf++) {
            float m = -1e30f;
#pragma unroll
            for (int nf = 0; nf < 8; nf++)
                m = fmaxf(m, fmaxf(acc[mf][nf][2 * hf], acc[mf][nf][2 * hf + 1]));
            mx[mf * 2 + hf] = m;
        }
#pragma unroll
    for (int ri = 0; ri < 4; ri++) {
        mx[ri] = fmaxf(mx[ri], __shfl_xor_sync(0xffffffffu, mx[ri], 1));
        mx[ri] = fmaxf(mx[ri], __shfl_xor_sync(0xffffffffu, mx[ri], 2));
    }
    if ((lane & 3) == 0) {
#pragma unroll
        for (int mf = 0; mf < 2; mf++)
#pragma unroll
            for (int hf = 0; hf < 2; hf++)
                redm[wn * 64 + wm * 32 + mf * 16 + hf * 8 + r4] = mx[mf * 2 + hf];
    }
    __syncthreads();
    float MX[4];
#pragma unroll
    for (int mf = 0; mf < 2; mf++)
#pragma unroll
        for (int hf = 0; hf < 2; hf++) {
            int row = wm * 32 + mf * 16 + hf * 8 + r4;
            float m = redm[row];
            m = fmaxf(m, redm[64 + row]);
            m = fmaxf(m, redm[128 + row]);
            m = fmaxf(m, redm[192 + row]);
            MX[mf * 2 + hf] = m;
        }
    float sm[4] = {0.f, 0.f, 0.f, 0.f};
#pragma unroll
    for (int mf = 0; mf < 2; mf++)
#pragma unroll
        for (int nf = 0; nf < 8; nf++)
#pragma unroll
            for (int hf = 0; hf < 2; hf++) {
                float e0 = __expf(acc[mf][nf][2 * hf] - MX[mf * 2 + hf]);
                float e1 = __expf(acc[mf][nf][2 * hf + 1] - MX[mf * 2 + hf]);
                acc[mf][nf][2 * hf] = e0;
                acc[mf][nf][2 * hf + 1] = e1;
                sm[mf * 2 + hf] += e0 + e1;
            }
#pragma unroll
    for (int ri = 0; ri < 4; ri++) {
        sm[ri] += __shfl_xor_sync(0xffffffffu, sm[ri], 1);
        sm[ri] += __shfl_xor_sync(0xffffffffu, sm[ri], 2);
    }
    if ((lane & 3) == 0) {
#pragma unroll
        for (int mf = 0; mf < 2; mf++)
#pragma unroll
            for (int hf = 0; hf < 2; hf++)
                reds[wn * 64 + wm * 32 + mf * 16 + hf * 8 + r4] = sm[mf * 2 + hf];
    }
    __syncthreads();
    float inv[4];
#pragma unroll
    for (int mf = 0; mf < 2; mf++)
#pragma unroll
        for (int hf = 0; hf < 2; hf++) {
            int row = wm * 32 + mf * 16 + hf * 8 + r4;
            float t = reds[row] + reds[64 + row] + reds[128 + row] + reds[192 + row];
            inv[mf * 2 + hf] = 1.f / t;
        }

#pragma unroll
    for (int mf = 0; mf < 2; mf++)
#pragma unroll
        for (int nf = 0; nf < 8; nf++) {
            int rowa = wm * 32 + mf * 16 + r4;
            int j = wn * 64 + nf * 8 + c2;
            *(uint32_t*)(sma + ATT_SM_P + swp(rowa, j * 2)) =
                pack_h2(acc[mf][nf][0] * inv[mf * 2], acc[mf][nf][1] * inv[mf * 2]);
            *(uint32_t*)(sma + ATT_SM_P + swp(rowa + 8, j * 2)) =
                pack_h2(acc[mf][nf][2] * inv[mf * 2 + 1], acc[mf][nf][3] * inv[mf * 2 + 1]);
        }
    __syncthreads();

    float oacc[2][2][4];
#pragma unroll
    for (int i = 0; i < 2; i++)
#pragma unroll
        for (int j = 0; j < 2; j++)
#pragma unroll
            for (int r = 0; r < 4; r++) oacc[i][j][r] = 0.f;

#pragma unroll
    for (int kk = 0; kk < 16; kk++) {
        uint32_t a[2][4];
#pragma unroll
        for (int mf = 0; mf < 2; mf++) {
            int row = wm * 32 + mf * 16 + (lane & 7) + ((lane >> 3) & 1) * 8;
            int kh = (lane >> 4) & 1;
            ldsm_x4(a[mf][0], a[mf][1], a[mf][2], a[mf][3],
                    sbase + ATT_SM_P + swp(row, kk * 32 + kh * 16));
        }
        uint32_t bf[2][2];
        {
            int kvrow = kk * 16 + (lane & 7) + ((lane >> 3) & 1) * 8;
            int nb = wn * 16 + ((lane >> 4) & 1) * 8;
            uint32_t r0, r1, r2, r3;
            ldsm_x4_t(r0, r1, r2, r3,
                      sbase + ATT_SM_V + sw128(kvrow * 128 + nb * 2));
            bf[0][0] = r0; bf[0][1] = r1; bf[1][0] = r2; bf[1][1] = r3;
        }
#pragma unroll
        for (int mf = 0; mf < 2; mf++)
#pragma unroll
            for (int nf = 0; nf < 2; nf++)
                mma_f16(oacc[mf][nf], a[mf][0], a[mf][1], a[mf][2], a[mf][3],
                        bf[nf][0], bf[nf][1]);
    }

#pragma unroll
    for (int mf = 0; mf < 2; mf++)
#pragma unroll
        for (int nf = 0; nf < 2; nf++) {
            int row = i0 + wm * 32 + mf * 16 + r4;
            int d = wn * 16 + nf * 8 + c2;
            __half* dst = ctx + ((long)(b * L_) + row) * H_ + hh * 64 + d;
            *(__half2*)dst = __floats2half2_rn(oacc[mf][nf][0], oacc[mf][nf][1]);
            *(__half2*)(dst + 8 * H_) = __floats2half2_rn(oacc[mf][nf][2], oacc[mf][nf][3]);
        }
}

// ---------------- warp-per-row embed + mask: 8 rows/block ----------------
__global__ __launch_bounds__(256) void embed_kernel(
    const int* __restrict__ x, const float* __restrict__ emb,
    float* __restrict__ h, __half* __restrict__ h16, int* __restrict__ mask) {
    const int warp = threadIdx.x >> 5, lane = threadIdx.x & 31;
    const long r = (long)blockIdx.x * 8 + warp;
    int tok = x[r];
    if (lane == 0) mask[r] = (tok != 0) ? 1 : 0;
    const float* e = emb + (long)tok * H_;
#pragma unroll
    for (int i = 0; i < 4; i++) {
        float4 f = *(const float4*)(e + i * 128 + lane * 4);
        *(float4*)(h + r * H_ + i * 128 + lane * 4) = f;
        *(uint2*)(h16 + r * H_ + i * 128 + lane * 4) =
            make_uint2(pack_h2(f.x, f.y), pack_h2(f.z, f.w));
    }
}

// ---------------- warp-per-row layernorm: no smem, no barriers ----------------
__global__ __launch_bounds__(256) void ln_kernel(
    const float* __restrict__ in, const __half* __restrict__ in16,
    float* __restrict__ out, __half* __restrict__ out16,
    const float* __restrict__ s, const float* __restrict__ b,
    int do_tanh) {
    const int warp = threadIdx.x >> 5, lane = threadIdx.x & 31;
    const long r = (long)blockIdx.x * 8 + warp;
    float v[16];
    if (in16) {
        const __half* x = in16 + r * H_;
#pragma unroll
        for (int i = 0; i < 4; i++) {
            uint2 u = *(const uint2*)(x + i * 128 + lane * 4);
            float2 f0 = __half22float2(*reinterpret_cast<__half2*>(&u.x));
            float2 f1 = __half22float2(*reinterpret_cast<__half2*>(&u.y));
            v[i * 4 + 0] = f0.x; v[i * 4 + 1] = f0.y;
            v[i * 4 + 2] = f1.x; v[i * 4 + 3] = f1.y;
        }
    } else {
        const float* x = in + r * H_;
#pragma unroll
        for (int i = 0; i < 4; i++) {
            float4 f = *(const float4*)(x + i * 128 + lane * 4);
            v[i * 4 + 0] = f.x; v[i * 4 + 1] = f.y;
            v[i * 4 + 2] = f.z; v[i * 4 + 3] = f.w;
        }
    }
    float sa = 0.f, sq = 0.f;
#pragma unroll
    for (int i = 0; i < 16; i++) { sa += v[i]; sq += v[i] * v[i]; }
#pragma unroll
    for (int o = 16; o; o >>= 1) {
        sa += __shfl_xor_sync(0xffffffffu, sa, o);
        sq += __shfl_xor_sync(0xffffffffu, sq, o);
    }
    float m = sa * (1.f / 512.f);
    float var = sq * (1.f / 512.f) - m * m;
    float inv = rsqrtf(var + 1e-5f);
#pragma unroll
    for (int i = 0; i < 4; i++) {
        float y[4];
#pragma unroll
        for (int q = 0; q < 4; q++) y[q] = (v[i * 4 + q] - m) * inv;
        if (s) {
            float4 sv = *(const float4*)(s + i * 128 + lane * 4);
            float4 bv = *(const float4*)(b + i * 128 + lane * 4);
            y[0] = y[0] * sv.x + bv.x; y[1] = y[1] * sv.y + bv.y;
            y[2] = y[2] * sv.z + bv.z; y[3] = y[3] * sv.w + bv.w;
        }
        if (do_tanh) {
#pragma unroll
            for (int q = 0; q < 4; q++) y[q] = tanhf(y[q]);
        }
        if (out)
            *(float4*)(out + r * H_ + i * 128 + lane * 4) =
                make_float4(y[0], y[1], y[2], y[3]);
        if (out16)
            *(uint2*)(out16 + r * H_ + i * 128 + lane * 4) =
                make_uint2(pack_h2(y[0], y[1]), pack_h2(y[2], y[3]));
    }
}

// ---------------- warp-per-row parse softmax (fp16 in-place, no barriers) ----------------
// 1 warp = 1 row (256 fp16, 8/lane). 8 rows/block -> 512 blocks.
__global__ __launch_bounds__(256) void softmax_head_kernel(
    __half* __restrict__ head16, const int* __restrict__ mask) {
    const int warp = threadIdx.x >> 5, lane = threadIdx.x & 31;
    const int bi = blockIdx.x * 8 + warp;
    const int b = bi >> 8, i = bi & 255;
    __half* row = head16 + (long)bi * L_;

    uint4 u = *(const uint4*)(row + lane * 8);
    int4 mk0 = *(const int4*)(mask + b * L_ + lane * 8);
    int4 mk1 = *(const int4*)(mask + b * L_ + lane * 8 + 4);
    float v[8];
    {
        float2 f;
        f = __half22float2(*reinterpret_cast<__half2*>(&u.x)); v[0] = f.x; v[1] = f.y;
        f = __half22float2(*reinterpret_cast<__half2*>(&u.y)); v[2] = f.x; v[3] = f.y;
        f = __half22float2(*reinterpret_cast<__half2*>(&u.z)); v[4] = f.x; v[5] = f.y;
        f = __half22float2(*reinterpret_cast<__half2*>(&u.w)); v[6] = f.x; v[7] = f.y;
    }
    int mk[8] = {mk0.x, mk0.y, mk0.z, mk0.w, mk1.x, mk1.y, mk1.z, mk1.w};
    float mx = -INFINITY;
#pragma unroll
    for (int q = 0; q < 8; q++) {
        v[q] = mk[q] ? v[q] * (1.f / 512.f) : -INFINITY;
        mx = fmaxf(mx, v[q]);
    }
#pragma unroll
    for (int o = 16; o; o >>= 1) mx = fmaxf(mx, __shfl_xor_sync(0xffffffffu, mx, o));
    float sum = 0.f;
#pragma unroll
    for (int q = 0; q < 8; q++) {
        v[q] = (v[q] == -INFINITY) ? 0.f : __expf(v[q] - mx);
        sum += v[q];
    }
#pragma unroll
    for (int o = 16; o; o >>= 1) sum += __shfl_xor_sync(0xffffffffu, sum, o);
    float inv = (sum > 0.f) ? 1.f / sum : 0.f;
    uint4 ou;
#pragma unroll
    for (int q = 0; q < 8; q++) {
        int j = lane * 8 + q;
        v[q] = (j == i) ? 0.f : v[q] * inv;
    }
    ou.x = pack_h2(v[0], v[1]); ou.y = pack_h2(v[2], v[3]);
    ou.z = pack_h2(v[4], v[5]); ou.w = pack_h2(v[6], v[7]);
    *(uint4*)(row + lane * 8) = ou;
}

// ---------------- head transpose (fp16) ----------------
__global__ void transpose16_kernel(const __half* __restrict__ head,
                                   __half* __restrict__ headT) {
    __shared__ __half t[32][34];
    int b = blockIdx.z;
    int i0 = blockIdx.y * 32, j0 = blockIdx.x * 32;
    const __half* src = head + (long)b * L_ * L_;
    t[threadIdx.y][threadIdx.x] = src[(long)(i0 + threadIdx.y) * L_ + j0 + threadIdx.x];
    __syncthreads();
    headT[(long)b * L_ * L_ + (long)(j0 + threadIdx.y) * L_ + i0 + threadIdx.x] =
        t[threadIdx.x][threadIdx.y];
}

// ---------------- host orchestration ----------------
#define GSM_SMALL (4 * (128 * 128 + 64 * 128))      // 98304 (4 stages)
#define GSM_BIG   (3 * (128 * 128 + 128 * 128))     // 98304 (3 stages)

static inline void launch_h(const __half* A, const __half* W, const float* bias,
                            const float* resid, float* C, __half* C16, const int* mask,
                            int M, int N, int Kd, int epilogue,
                            int conv_mode = 0, int strideA = -1, int strideW = -1,
                            int batch = 1, long sA = 0, long sB = 0, long sC = 0) {
    if (strideA < 0) strideA = Kd;
    if (strideW < 0) strideW = Kd;
    if (N <= 512) {
        dim3 g((N + 63) / 64, M / 128, batch);
        gemm_h<4, 2, 2, 4, 4><<<g, 256, GSM_SMALL>>>(A, W, bias, resid, C, C16, mask,
                                                     M, N, Kd, strideA, strideW,
                                                     sA, sB, sC, epilogue, conv_mode);
    } else {
        dim3 g((N + 127) / 128, M / 128, batch);
        gemm_h<2, 4, 4, 4, 3><<<g, 256, GSM_BIG>>>(A, W, bias, resid, C, C16, mask,
                                                   M, N, Kd, strideA, strideW,
                                                   sA, sB, sC, epilogue, conv_mode);
    }
}

extern "C" void kernel_launch(void* const* d_in, const int* in_sizes, int n_in,
                              void* d_out, int out_size) {
    const int*   x        = (const int*)d_in[0];
    const float* emb      = (const float*)d_in[2];
    const float* conv_w   = (const float*)d_in[3];
    const float* conv_b   = (const float*)d_in[4];
    const float* parent_w = (const float*)d_in[5];
    const float* parent_b = (const float*)d_in[6];
    const float* child_w  = (const float*)d_in[7];
    const float* child_b  = (const float*)d_in[8];
    const float* rel_w    = (const float*)d_in[9];
    const float* qkv_w    = (const float*)d_in[10];
    const float* qkv_b    = (const float*)d_in[11];
    const float* out_w    = (const float*)d_in[12];
    const float* out_b    = (const float*)d_in[13];
    const float* ln1_s    = (const float*)d_in[14];
    const float* ln1_b    = (const float*)d_in[15];
    const float* ln2_s    = (const float*)d_in[16];
    const float* ln2_b    = (const float*)d_in[17];
    const float* ff1_w    = (const float*)d_in[18];
    const float* ff1_b    = (const float*)d_in[19];
    const float* ff2_w    = (const float*)d_in[20];
    const float* ff2_b    = (const float*)d_in[21];
    const float* norm_s   = (const float*)d_in[22];
    const float* norm_b   = (const float*)d_in[23];
    const float* out_bias = (const float*)d_in[24];
    float* out = (float*)d_out;

    void *p;
    cudaGetSymbolAddress(&p, g_h);        float*  h       = (float*)p;
    cudaGetSymbolAddress(&p, g_pcb);      float*  pcb     = (float*)p;
    cudaGetSymbolAddress(&p, g_mask);     int*    mask    = (int*)p;
    cudaGetSymbolAddress(&p, g_head16);   __half* head16  = (__half*)p;
    cudaGetSymbolAddress(&p, g_headT16);  __half* headT16 = (__half*)p;
    cudaGetSymbolAddress(&p, g_h16);      __half* h16     = (__half*)p;
    cudaGetSymbolAddress(&p, g_hn16);     __half* hn16    = (__half*)p;
    cudaGetSymbolAddress(&p, g_pc16);     __half* pc16    = (__half*)p;
    cudaGetSymbolAddress(&p, g_qkv16);    __half* qkv16   = (__half*)p;
    cudaGetSymbolAddress(&p, g_ctx16);    __half* ctx16   = (__half*)p;
    cudaGetSymbolAddress(&p, g_ff16);     __half* ff16    = (__half*)p;
    cudaGetSymbolAddress(&p, g_convT16);  __half* convT16 = (__half*)p;
    cudaGetSymbolAddress(&p, g_qkvw16);   __half* qkvw16  = (__half*)p;
    cudaGetSymbolAddress(&p, g_outw16);   __half* outw16  = (__half*)p;
    cudaGetSymbolAddress(&p, g_ff1w16);   __half* ff1w16  = (__half*)p;
    cudaGetSymbolAddress(&p, g_ff2w16);   __half* ff2w16  = (__half*)p;
    cudaGetSymbolAddress(&p, g_pcw16);    __half* pcw16   = (__half*)p;
    cudaGetSymbolAddress(&p, g_emb16);    __half* emb16   = (__half*)p;

    cudaFuncSetAttribute(attn_mma, cudaFuncAttributeMaxDynamicSharedMemorySize, ATT_SMEM);
    cudaFuncSetAttribute(gemm_h<4, 2, 2, 4, 4>,
                         cudaFuncAttributeMaxDynamicSharedMemorySize, GSM_SMALL);
    cudaFuncSetAttribute(gemm_h<2, 4, 4, 4, 3>,
                         cudaFuncAttributeMaxDynamicSharedMemorySize, GSM_BIG);

    // ---- weight conversions ----
    convw_transpose16<<<dim3(16, 16, P_ * KW_), dim3(32, 32)>>>(conv_w, convT16);
    {
        CvtJobs j;
        j.src[0] = qkv_w;    j.dst[0] = qkvw16;           j.n4[0] = NL_ * 3 * H_ * H_ / 4;
        j.src[1] = out_w;    j.dst[1] = outw16;           j.n4[1] = NL_ * H_ * H_ / 4;
        j.src[2] = ff1_w;    j.dst[2] = ff1w16;           j.n4[2] = NL_ * DFF_ * H_ / 4;
        j.src[3] = ff2_w;    j.dst[3] = ff2w16;           j.n4[3] = NL_ * H_ * DFF_ / 4;
        j.src[4] = parent_w; j.dst[4] = pcw16;            j.n4[4] = H_ * H_ / 4;
        j.src[5] = child_w;  j.dst[5] = pcw16 + 512 * H_; j.n4[5] = H_ * H_ / 4;
        j.src[6] = emb;      j.dst[6] = emb16;            j.n4[6] = NTOK_ * H_ / 4;
        int total4 = 0;
        for (int k = 0; k < 7; k++) total4 += j.n4[k];
        cvt_multi<<<(total4 + 255) / 256, 256>>>(j, total4);
    }
    concat_bias<<<4, 256>>>(parent_b, child_b, pcb);

    // ---- embedding + mask ----
    embed_kernel<<<BL_ / 8, 256>>>(x, emb, h, h16, mask);

    // ---- parser ----
    for (int pl = 0; pl < P_; pl++) {
        launch_h(h16, convT16 + (long)pl * H_ * KW_ * H_, conv_b + pl * H_,
                 nullptr, nullptr, hn16, mask, BL_, H_, KW_ * H_, 0,
                 /*conv_mode=*/1, /*strideA=*/H_);
        ln_kernel<<<BL_ / 8, 256>>>(nullptr, hn16, nullptr, h16, nullptr, nullptr, 1);
    }

    // ---- parent+child combined GEMM ----
    launch_h(h16, pcw16, pcb, nullptr, nullptr, pc16, mask, BL_, 1024, H_, 0);

    // ---- parse logits + softmax + transpose ----
    launch_h(pc16 + 512, pc16, nullptr, nullptr, nullptr, head16, mask,
             L_, L_, H_, 0, 0, /*strideA=*/1024, /*strideW=*/1024,
             B_, (long)L_ * 1024, (long)L_ * 1024, (long)L_ * L_);
    softmax_head_kernel<<<BL_ / 8, 256>>>(head16, mask);
    transpose16_kernel<<<dim3(8, 8, B_), dim3(32, 32)>>>(head16, headT16);

    // ---- transformer ----
    for (int i = 0; i < NL_; i++) {
        ln_kernel<<<BL_ / 8, 256>>>(h, nullptr, nullptr, hn16,
                                    ln1_s + i * H_, ln1_b + i * H_, 0);
        launch_h(hn16, qkvw16 + (long)i * 3 * H_ * H_, qkv_b + i * 3 * H_,
                 nullptr, nullptr, qkv16, mask, BL_, 3 * H_, H_, 0);
        attn_mma<<<dim3(4, NH_, B_), 256, ATT_SMEM>>>(qkv16, head16, headT16, mask,
                                                      rel_w, i, ctx16);
        launch_h(ctx16, outw16 + (long)i * H_ * H_, out_b + i * H_, h, h, nullptr, mask,
                 BL_, H_, H_, 0);
        ln_kernel<<<BL_ / 8, 256>>>(h, nullptr, nullptr, hn16,
                                    ln2_s + i * H_, ln2_b + i * H_, 0);
        launch_h(hn16, ff1w16 + (long)i * DFF_ * H_, ff1_b + i * DFF_,
                 nullptr, nullptr, ff16, mask, BL_, DFF_, H_, 1);
        launch_h(ff16, ff2w16 + (long)i * H_ * DFF_, ff2_b + i * H_, h, h, nullptr, mask,
                 BL_, H_, DFF_, 0);
    }

    // ---- final LN + tied output ----
    ln_kernel<<<BL_ / 8, 256>>>(h, nullptr, nullptr, hn16, norm_s, norm_b, 0);
    launch_h(hn16, emb16, out_bias, nullptr, out, nullptr, mask, BL_, NTOK_, H_, 0);
}